// round 1
// baseline (speedup 1.0000x reference)
#include <cuda_runtime.h>
#include <math.h>

#define Nn 32
#define Cc 128
#define Hh 48
#define Ww 48
#define Pp 2304            // H*W
#define Kk 64
#define Ss 4
#define Ll 3
#define Rr 21
#define Jj 512             // 64 score + 256 shadow + 192 app
#define MTOT (Nn*Pp)       // 73728
#define NCH 12             // P-chunks in vlad GEMM (2304/12 = 192)

// ---------------- scratch (device globals; no allocs allowed) ----------------
__device__ float g_xn[(size_t)Nn*Pp*Cc];        // normalized x, pixel-major [n,p,c]
__device__ float g_wall[Jj*Cc];                 // stacked weights [j,c]
__device__ float g_scores[(size_t)MTOT*Jj];     // [m, j]
__device__ float g_a[(size_t)Nn*Kk*Pp];         // a * sal_pix  [n,k,p]
__device__ float g_app[(size_t)Nn*Ll*Kk*Pp];    // relu(app)    [n, l*K+k, p]
__device__ float g_sal[Nn*Kk*Rr];               // region sums  [n,k,r]
__device__ float g_awsum[Nn*Kk];
__device__ float g_part[(size_t)Nn*NCH*Kk*Cc];  // vlad partials
__device__ float g_nrm[Nn];

// region table: {level, h0, h1, w0, w1}
__device__ const int c_reg[21][5] = {
  {0, 0,48,  0,48},
  {1, 0,32,  0,32},{1, 0,32, 16,48},{1,16,48,  0,32},{1,16,48, 16,48},
  {2, 0,19,  0,19},{2, 0,19,  9,29},{2, 0,19, 19,39},{2, 0,19, 29,48},
  {2, 9,29,  0,19},{2, 9,29,  9,29},{2, 9,29, 19,39},{2, 9,29, 29,48},
  {2,19,39,  0,19},{2,19,39,  9,29},{2,19,39, 19,39},{2,19,39, 29,48},
  {2,29,48,  0,19},{2,29,48,  9,29},{2,29,48, 19,39},{2,29,48, 29,48},
};

// membership helpers: which windows (per-dim) contain coordinate h
__device__ __forceinline__ void memb1(int h, int& lo, int& hi) {
  lo = (h >= 32) ? 1 : 0;
  hi = (h >= 16) ? 1 : 0;
}
__device__ __forceinline__ void memb2(int h, int& lo, int& hi) {
  lo = (h >= 19) ? ((h - 9) / 10) : 0;
  int m = (h + 1) / 10;
  hi = m > 3 ? 3 : m;
}

// ---------------- K1: per-pixel L2 normalize + transpose to [n,p,c] ----------
__global__ void k_norm(const float* __restrict__ x) {
  int n = blockIdx.y, p0 = blockIdx.x * 32;
  __shared__ float Xs[128][33];
  __shared__ float inv[32];
  const float* xb = x + (size_t)n * Cc * Pp;
  int tid = threadIdx.x;
  #pragma unroll
  for (int i = 0; i < 16; i++) {
    int idx = i * 256 + tid;
    int c = idx >> 5, pp = idx & 31;
    Xs[c][pp] = xb[(size_t)c * Pp + p0 + pp];
  }
  __syncthreads();
  {
    int pp = tid >> 3, part = tid & 7;
    float s = 0.f;
    #pragma unroll
    for (int c = 0; c < 16; c++) { float v = Xs[part + c * 8][pp]; s += v * v; }
    s += __shfl_down_sync(0xffffffffu, s, 4);
    s += __shfl_down_sync(0xffffffffu, s, 2);
    s += __shfl_down_sync(0xffffffffu, s, 1);
    if (part == 0) inv[pp] = 1.0f / fmaxf(sqrtf(s), 1e-12f);
  }
  __syncthreads();
  float* xo = g_xn + (size_t)(n * Pp + p0) * Cc;
  #pragma unroll
  for (int i = 0; i < 16; i++) {
    int idx = i * 256 + tid;
    int pp = idx >> 7, c = idx & 127;
    xo[pp * 128 + c] = Xs[c][pp] * inv[pp];
  }
}

// ---------------- K2: assemble stacked weight matrix + zero norms ------------
__global__ void k_wall(const float* __restrict__ cw, const float* __restrict__ shw,
                       const float* __restrict__ appw) {
  int idx = blockIdx.x * 256 + threadIdx.x;
  if (idx < 32) g_nrm[idx] = 0.f;
  if (idx >= Jj * Cc) return;
  int j = idx >> 7, c = idx & 127;
  float v;
  if (j < 64)       v = cw[j * 128 + c];
  else if (j < 320) v = shw[(j - 64) * 128 + c];
  else              v = appw[(j - 320) * 128 + c];
  g_wall[idx] = v;
}

// ---------------- K3: big SGEMM  scores[m,j] = xn[m,:] . wall[j,:] -----------
__global__ void k_gemm() {
  __shared__ float As[32][68];
  __shared__ float Bs[32][68];
  int m0 = blockIdx.y * 64, j0 = blockIdx.x * 64;
  int tid = threadIdx.x;
  int tx = tid & 15, ty = tid >> 4;
  float acc[4][4] = {};
  #pragma unroll
  for (int k0 = 0; k0 < 128; k0 += 32) {
    #pragma unroll
    for (int i = 0; i < 2; i++) {
      int t = i * 256 + tid;          // 0..511 float4 slots
      int r = t >> 3, c4 = t & 7;
      float4 v = *(const float4*)(g_xn + (size_t)(m0 + r) * 128 + k0 + c4 * 4);
      As[c4 * 4 + 0][r] = v.x; As[c4 * 4 + 1][r] = v.y;
      As[c4 * 4 + 2][r] = v.z; As[c4 * 4 + 3][r] = v.w;
      float4 w = *(const float4*)(g_wall + (size_t)(j0 + r) * 128 + k0 + c4 * 4);
      Bs[c4 * 4 + 0][r] = w.x; Bs[c4 * 4 + 1][r] = w.y;
      Bs[c4 * 4 + 2][r] = w.z; Bs[c4 * 4 + 3][r] = w.w;
    }
    __syncthreads();
    #pragma unroll
    for (int kk = 0; kk < 32; kk++) {
      float4 a4 = *(const float4*)&As[kk][ty * 4];
      float4 b4 = *(const float4*)&Bs[kk][tx * 4];
      acc[0][0] += a4.x * b4.x; acc[0][1] += a4.x * b4.y; acc[0][2] += a4.x * b4.z; acc[0][3] += a4.x * b4.w;
      acc[1][0] += a4.y * b4.x; acc[1][1] += a4.y * b4.y; acc[1][2] += a4.y * b4.z; acc[1][3] += a4.y * b4.w;
      acc[2][0] += a4.z * b4.x; acc[2][1] += a4.z * b4.y; acc[2][2] += a4.z * b4.z; acc[2][3] += a4.z * b4.w;
      acc[3][0] += a4.w * b4.x; acc[3][1] += a4.w * b4.y; acc[3][2] += a4.w * b4.z; acc[3][3] += a4.w * b4.w;
    }
    __syncthreads();
  }
  #pragma unroll
  for (int i = 0; i < 4; i++) {
    float4 v = make_float4(acc[i][0], acc[i][1], acc[i][2], acc[i][3]);
    *(float4*)(g_scores + (size_t)(m0 + ty * 4 + i) * Jj + j0 + tx * 4) = v;
  }
}

// ---------------- K4: per-pixel softmax + shadow softmax + relu(app) ---------
__global__ void k_epilogue() {
  int m = blockIdx.x * 8 + (threadIdx.x >> 5);
  int lane = threadIdx.x & 31;
  const float* sc = g_scores + (size_t)m * Jj;
  int n = m / Pp, p = m % Pp;

  float s1 = sc[lane], s2 = sc[lane + 32];
  float mx = fmaxf(s1, s2);
  #pragma unroll
  for (int o = 16; o; o >>= 1) mx = fmaxf(mx, __shfl_xor_sync(0xffffffffu, mx, o));
  float e1 = expf(s1 - mx), e2 = expf(s2 - mx);
  float z = e1 + e2;
  #pragma unroll
  for (int o = 16; o; o >>= 1) z += __shfl_xor_sync(0xffffffffu, z, o);
  float a1 = e1 / z, a2 = e2 / z;

  #pragma unroll
  for (int half = 0; half < 2; half++) {
    int k = lane + half * 32;
    float s = half ? s2 : s1;
    const float* shp = sc + 64 + k * 4;
    float h0 = shp[0], h1 = shp[1], h2 = shp[2], h3 = shp[3];
    float mxs = fmaxf(fmaxf(fmaxf(h0, h1), fmaxf(h2, h3)), s);
    float es = expf(s - mxs);
    float d = es + expf(h0 - mxs) + expf(h1 - mxs) + expf(h2 - mxs) + expf(h3 - mxs);
    float av = (half ? a2 : a1) * (es / d);
    g_a[((size_t)n * Kk + k) * Pp + p] = av;
  }
  #pragma unroll
  for (int q = 0; q < 6; q++) {
    int jj = lane * 6 + q;
    g_app[((size_t)n * (Ll * Kk) + jj) * Pp + p] = fmaxf(sc[320 + jj], 0.f);
  }
}

// ---------------- K5: region sums  sal[n,k,r] --------------------------------
__global__ void k_sal() {
  int k = blockIdx.x, n = blockIdx.y;
  int tid = threadIdx.x;
  __shared__ float red[256];
  for (int r = 0; r < Rr; r++) {
    int l = c_reg[r][0], h0 = c_reg[r][1], h1 = c_reg[r][2], w0 = c_reg[r][3], w1 = c_reg[r][4];
    const float* ap = g_app + ((size_t)n * (Ll * Kk) + l * Kk + k) * Pp;
    int wd = w1 - w0, tot = (h1 - h0) * wd;
    float s = 0.f;
    for (int i = tid; i < tot; i += 256) {
      int hh = h0 + i / wd, ww = w0 + i % wd;
      s += ap[hh * Ww + ww];
    }
    red[tid] = s; __syncthreads();
    for (int off = 128; off; off >>= 1) {
      if (tid < off) red[tid] += red[tid + off];
      __syncthreads();
    }
    if (tid == 0) g_sal[((size_t)n * Kk + k) * Rr + r] = red[0];
    __syncthreads();
  }
}

// ---------------- K6: awsum[n,k] = sum_p a*w --------------------------------
__global__ void k_awsum() {
  int k = blockIdx.x, n = blockIdx.y;
  int tid = threadIdx.x;
  __shared__ float salsh[Rr];
  __shared__ float red[256];
  if (tid < Rr) salsh[tid] = g_sal[((size_t)n * Kk + k) * Rr + tid];
  __syncthreads();
  const float* ab = g_a + ((size_t)n * Kk + k) * Pp;
  float s = 0.f;
  for (int p = tid; p < Pp; p += 256) {
    int h = p / Ww, w = p % Ww;
    float wsum = salsh[0];
    int rl, rh, cl, ch;
    memb1(h, rl, rh); memb1(w, cl, ch);
    for (int i = rl; i <= rh; i++)
      for (int j = cl; j <= ch; j++) wsum += salsh[1 + 2 * i + j];
    memb2(h, rl, rh); memb2(w, cl, ch);
    for (int i = rl; i <= rh; i++)
      for (int j = cl; j <= ch; j++) wsum += salsh[5 + 4 * i + j];
    s += ab[p] * wsum;
  }
  red[tid] = s; __syncthreads();
  for (int off = 128; off; off >>= 1) {
    if (tid < off) red[tid] += red[tid + off];
    __syncthreads();
  }
  if (tid == 0) g_awsum[n * Kk + k] = red[0];
}

// ---------------- K7: vlad GEMM partials  part = aw[K,Pchunk] x xn[Pchunk,C] -
__global__ void k_vlad() {
  int n = blockIdx.y, chk = blockIdx.x;
  int p0base = chk * (Pp / NCH);               // 192 pixels per chunk
  __shared__ float Xs[32][132];
  __shared__ float awS[64][33];
  __shared__ float salsh[64][22];
  __shared__ unsigned char msh[8][32];
  int tid = threadIdx.x;
  int tx = tid & 15, ty = tid >> 4;

  for (int i = tid; i < 64 * Rr; i += 256)
    salsh[i / Rr][i % Rr] = g_sal[(size_t)n * Kk * Rr + i];

  float acc[4][8] = {};
  for (int t = 0; t < 6; t++) {
    int p0 = p0base + t * 32;
    __syncthreads();
    #pragma unroll
    for (int i = 0; i < 4; i++) {
      int idx = i * 256 + tid;                 // float4 slot
      int pp = idx >> 5, c4 = idx & 31;
      float4 v = *(const float4*)(g_xn + (size_t)(n * Pp + p0 + pp) * 128 + c4 * 4);
      *(float4*)&Xs[pp][c4 * 4] = v;
    }
    if (tid < 32) {
      int p = p0 + tid;
      int h = p / Ww, w = p % Ww;
      int a, b;
      memb1(h, a, b); msh[0][tid] = a; msh[1][tid] = b;
      memb1(w, a, b); msh[2][tid] = a; msh[3][tid] = b;
      memb2(h, a, b); msh[4][tid] = a; msh[5][tid] = b;
      memb2(w, a, b); msh[6][tid] = a; msh[7][tid] = b;
    }
    __syncthreads();
    #pragma unroll
    for (int i = 0; i < 8; i++) {
      int idx = i * 256 + tid;
      int k = idx >> 5, pp = idx & 31;
      float av = g_a[((size_t)n * Kk + k) * Pp + p0 + pp];
      const float* sk = &salsh[k][0];
      float wsum = sk[0];
      int r1l = msh[0][pp], r1h = msh[1][pp], c1l = msh[2][pp], c1h = msh[3][pp];
      int r2l = msh[4][pp], r2h = msh[5][pp], c2l = msh[6][pp], c2h = msh[7][pp];
      for (int ii = r1l; ii <= r1h; ii++)
        for (int jj = c1l; jj <= c1h; jj++) wsum += sk[1 + 2 * ii + jj];
      for (int ii = r2l; ii <= r2h; ii++)
        for (int jj = c2l; jj <= c2h; jj++) wsum += sk[5 + 4 * ii + jj];
      awS[k][pp] = av * wsum;
    }
    __syncthreads();
    #pragma unroll
    for (int pp = 0; pp < 32; pp++) {
      float a0 = awS[ty * 4 + 0][pp];
      float a1 = awS[ty * 4 + 1][pp];
      float a2 = awS[ty * 4 + 2][pp];
      float a3 = awS[ty * 4 + 3][pp];
      float4 x0 = *(const float4*)&Xs[pp][tx * 8];
      float4 x1 = *(const float4*)&Xs[pp][tx * 8 + 4];
      acc[0][0] += a0 * x0.x; acc[0][1] += a0 * x0.y; acc[0][2] += a0 * x0.z; acc[0][3] += a0 * x0.w;
      acc[0][4] += a0 * x1.x; acc[0][5] += a0 * x1.y; acc[0][6] += a0 * x1.z; acc[0][7] += a0 * x1.w;
      acc[1][0] += a1 * x0.x; acc[1][1] += a1 * x0.y; acc[1][2] += a1 * x0.z; acc[1][3] += a1 * x0.w;
      acc[1][4] += a1 * x1.x; acc[1][5] += a1 * x1.y; acc[1][6] += a1 * x1.z; acc[1][7] += a1 * x1.w;
      acc[2][0] += a2 * x0.x; acc[2][1] += a2 * x0.y; acc[2][2] += a2 * x0.z; acc[2][3] += a2 * x0.w;
      acc[2][4] += a2 * x1.x; acc[2][5] += a2 * x1.y; acc[2][6] += a2 * x1.z; acc[2][7] += a2 * x1.w;
      acc[3][0] += a3 * x0.x; acc[3][1] += a3 * x0.y; acc[3][2] += a3 * x0.z; acc[3][3] += a3 * x0.w;
      acc[3][4] += a3 * x1.x; acc[3][5] += a3 * x1.y; acc[3][6] += a3 * x1.z; acc[3][7] += a3 * x1.w;
    }
  }
  float* outp = g_part + ((size_t)n * NCH + chk) * Kk * Cc;
  #pragma unroll
  for (int i = 0; i < 4; i++) {
    int k = ty * 4 + i;
    float4 v0 = make_float4(acc[i][0], acc[i][1], acc[i][2], acc[i][3]);
    float4 v1 = make_float4(acc[i][4], acc[i][5], acc[i][6], acc[i][7]);
    *(float4*)&outp[k * 128 + tx * 8]     = v0;
    *(float4*)&outp[k * 128 + tx * 8 + 4] = v1;
  }
}

// ---------------- K8: reduce partials, subtract centroid, intra-norm ---------
__global__ void k_fin1(const float* __restrict__ centroids,
                       const float* __restrict__ cw, float* __restrict__ out) {
  int k = blockIdx.x, n = blockIdx.y, c = threadIdx.x;   // 128 threads
  float s = 0.f;
  #pragma unroll
  for (int ch = 0; ch < NCH; ch++)
    s += g_part[(((size_t)n * NCH + ch) * Kk + k) * Cc + c];
  float v = s - centroids[k * 128 + c] * g_awsum[n * Kk + k];
  __shared__ float red[128];
  __shared__ float invs;
  red[c] = v * v; __syncthreads();
  for (int off = 64; off; off >>= 1) {
    if (c < off) red[c] += red[c + off];
    __syncthreads();
  }
  if (c == 0) invs = 1.0f / fmaxf(sqrtf(red[0]), 1e-12f);
  __syncthreads();
  float val = v * invs * cw[k];
  out[(size_t)n * (Kk * Cc) + k * 128 + c] = val;
  red[c] = val * val; __syncthreads();
  for (int off = 64; off; off >>= 1) {
    if (c < off) red[c] += red[c + off];
    __syncthreads();
  }
  if (c == 0) atomicAdd(&g_nrm[n], red[0]);
}

// ---------------- K9: global normalization ----------------------------------
__global__ void k_fin2(float* __restrict__ out) {
  int n = blockIdx.y;
  int i = blockIdx.x * 256 + threadIdx.x;
  float inv = 1.0f / fmaxf(sqrtf(g_nrm[n]), 1e-12f);
  out[(size_t)n * (Kk * Cc) + i] *= inv;
}

// ---------------- launcher ---------------------------------------------------
extern "C" void kernel_launch(void* const* d_in, const int* in_sizes, int n_in,
                              void* d_out, int out_size) {
  const float* x         = (const float*)d_in[0];  // [N,C,H,W]
  const float* centroids = (const float*)d_in[1];  // [K,C]
  const float* conv_w    = (const float*)d_in[2];  // [K,C]
  const float* shadow_w  = (const float*)d_in[3];  // [K*S,C]
  const float* app_w     = (const float*)d_in[4];  // [L,K,C]
  const float* clw       = (const float*)d_in[5];  // [K]
  float* out = (float*)d_out;

  k_norm<<<dim3(Pp / 32, Nn), 256>>>(x);
  k_wall<<<dim3((Jj * Cc + 255) / 256), 256>>>(conv_w, shadow_w, app_w);
  k_gemm<<<dim3(Jj / 64, MTOT / 64), 256>>>();
  k_epilogue<<<dim3(MTOT / 8), 256>>>();
  k_sal<<<dim3(Kk, Nn), 256>>>();
  k_awsum<<<dim3(Kk, Nn), 256>>>();
  k_vlad<<<dim3(NCH, Nn), 256>>>();
  k_fin1<<<dim3(Kk, Nn), 128>>>(centroids, clw, out);
  k_fin2<<<dim3(Kk * Cc / 256, Nn), 256>>>(out);
}

// round 2
// speedup vs baseline: 1.3314x; 1.3314x over previous
#include <cuda_runtime.h>
#include <math.h>

#define Nn 32
#define Cc 128
#define Hh 48
#define Ww 48
#define Pp 2304            // H*W
#define Kk 64
#define Ss 4
#define Ll 3
#define Rr 21
#define Jj 512             // 64 score + 256 shadow + 192 app
#define MTOT (Nn*Pp)       // 73728
#define NCH 12             // P-chunks in vlad GEMM (2304/12 = 192)

#define SST 513            // score tile smem stride (odd => conflict-free columns)
#define BST 21             // Bs stride (odd => conflict-free j-interleaved reads)

// ---------------- scratch (device globals; no allocs allowed) ----------------
__device__ float g_xn[(size_t)Nn*Pp*Cc];        // normalized x, pixel-major [n,p,c]
__device__ float g_wall[Jj*Cc];                 // stacked weights [j,c]
__device__ float g_a[(size_t)Nn*Kk*Pp];         // a * sal_pix  [n,k,p]
__device__ float g_app[(size_t)Nn*Ll*Kk*Pp];    // relu(app)    [n, l*K+k, p]
__device__ float g_sal[Nn*Kk*Rr];               // region sums  [n,k,r]
__device__ float g_awsum[Nn*Kk];
__device__ float g_part[(size_t)Nn*NCH*Kk*Cc];  // vlad partials
__device__ float g_nrm[Nn];

// region table: {level, h0, h1, w0, w1}
__device__ const int c_reg[21][5] = {
  {0, 0,48,  0,48},
  {1, 0,32,  0,32},{1, 0,32, 16,48},{1,16,48,  0,32},{1,16,48, 16,48},
  {2, 0,19,  0,19},{2, 0,19,  9,29},{2, 0,19, 19,39},{2, 0,19, 29,48},
  {2, 9,29,  0,19},{2, 9,29,  9,29},{2, 9,29, 19,39},{2, 9,29, 29,48},
  {2,19,39,  0,19},{2,19,39,  9,29},{2,19,39, 19,39},{2,19,39, 29,48},
  {2,29,48,  0,19},{2,29,48,  9,29},{2,29,48, 19,39},{2,29,48, 29,48},
};

// membership helpers: which windows (per-dim) contain coordinate h
__device__ __forceinline__ void memb1(int h, int& lo, int& hi) {
  lo = (h >= 32) ? 1 : 0;
  hi = (h >= 16) ? 1 : 0;
}
__device__ __forceinline__ void memb2(int h, int& lo, int& hi) {
  lo = (h >= 19) ? ((h - 9) / 10) : 0;
  int m = (h + 1) / 10;
  hi = m > 3 ? 3 : m;
}

// ---------------- K1: per-pixel L2 normalize + transpose to [n,p,c] ----------
__global__ void k_norm(const float* __restrict__ x) {
  int n = blockIdx.y, p0 = blockIdx.x * 32;
  __shared__ float Xs[128][33];
  __shared__ float inv[32];
  const float* xb = x + (size_t)n * Cc * Pp;
  int tid = threadIdx.x;
  #pragma unroll
  for (int i = 0; i < 16; i++) {
    int idx = i * 256 + tid;
    int c = idx >> 5, pp = idx & 31;
    Xs[c][pp] = xb[(size_t)c * Pp + p0 + pp];
  }
  __syncthreads();
  {
    int pp = tid >> 3, part = tid & 7;
    float s = 0.f;
    #pragma unroll
    for (int c = 0; c < 16; c++) { float v = Xs[part + c * 8][pp]; s += v * v; }
    s += __shfl_down_sync(0xffffffffu, s, 4);
    s += __shfl_down_sync(0xffffffffu, s, 2);
    s += __shfl_down_sync(0xffffffffu, s, 1);
    if (part == 0) inv[pp] = 1.0f / fmaxf(sqrtf(s), 1e-12f);
  }
  __syncthreads();
  float* xo = g_xn + (size_t)(n * Pp + p0) * Cc;
  #pragma unroll
  for (int i = 0; i < 16; i++) {
    int idx = i * 256 + tid;
    int pp = idx >> 7, c = idx & 127;
    xo[pp * 128 + c] = Xs[c][pp] * inv[pp];
  }
}

// ---------------- K2: assemble stacked weight matrix + zero accumulators -----
__global__ void k_wall(const float* __restrict__ cw, const float* __restrict__ shw,
                       const float* __restrict__ appw) {
  int idx = blockIdx.x * 256 + threadIdx.x;
  if (idx < 32) g_nrm[idx] = 0.f;
  if (idx < Nn * Kk) g_awsum[idx] = 0.f;
  if (idx >= Jj * Cc) return;
  int j = idx >> 7, c = idx & 127;
  float v;
  if (j < 64)       v = cw[j * 128 + c];
  else if (j < 320) v = shw[(j - 64) * 128 + c];
  else              v = appw[(j - 320) * 128 + c];
  g_wall[idx] = v;
}

// ---------------- K3: fused SGEMM + softmax/shadow/relu epilogue -------------
// Block: 32 pixels x all 512 outputs. acc: 4 px x 16 j per thread,
// j interleaved: thread tx owns j = tx + 32*jj.
__global__ void k_gemm_epi() {
  extern __shared__ float smem[];
  float* As = smem;                 // [16][36] during GEMM
  float* Bs = smem + 16 * 36;       // [512][21] during GEMM
  float* Ssc = smem;                // [32][513] after GEMM (overlaps As/Bs)

  int tid = threadIdx.x;
  int tx = tid & 31, ty = tid >> 5;       // ty = warp id = pixel group
  int m0 = blockIdx.x * 32;
  int n = m0 / Pp, p0 = m0 % Pp;

  float acc[4][16] = {};

  #pragma unroll 1
  for (int kc = 0; kc < 128; kc += 16) {
    // load As[16][32] transposed (k-major), stride 36
    if (tid < 128) {
      int pp = tid >> 2, q = tid & 3;
      float4 v = *(const float4*)(g_xn + (size_t)(n * Pp + p0 + pp) * 128 + kc + q * 4);
      As[(q * 4 + 0) * 36 + pp] = v.x;
      As[(q * 4 + 1) * 36 + pp] = v.y;
      As[(q * 4 + 2) * 36 + pp] = v.z;
      As[(q * 4 + 3) * 36 + pp] = v.w;
    }
    // load Bs[512][16] j-major, stride 21
    #pragma unroll
    for (int i = 0; i < 8; i++) {
      int idx = i * 256 + tid;
      int j = idx >> 2, q = idx & 3;
      float4 v = *(const float4*)(g_wall + (size_t)j * 128 + kc + q * 4);
      Bs[j * BST + q * 4 + 0] = v.x;
      Bs[j * BST + q * 4 + 1] = v.y;
      Bs[j * BST + q * 4 + 2] = v.z;
      Bs[j * BST + q * 4 + 3] = v.w;
    }
    __syncthreads();
    #pragma unroll
    for (int kk = 0; kk < 16; kk++) {
      float4 a = *(const float4*)&As[kk * 36 + ty * 4];
      #pragma unroll
      for (int jj = 0; jj < 16; jj++) {
        float bv = Bs[(tx + 32 * jj) * BST + kk];
        acc[0][jj] += a.x * bv;
        acc[1][jj] += a.y * bv;
        acc[2][jj] += a.z * bv;
        acc[3][jj] += a.w * bv;
      }
    }
    __syncthreads();
  }

  // stage scores into SMEM tile [32][513]
  #pragma unroll
  for (int i = 0; i < 4; i++) {
    int pp = ty * 4 + i;
    #pragma unroll
    for (int jj = 0; jj < 16; jj++)
      Ssc[pp * SST + tx + 32 * jj] = acc[i][jj];
  }
  __syncthreads();

  // ---- per-pixel epilogue: each warp owns 4 pixels, lane handles k, k+32 ----
  #pragma unroll
  for (int i = 0; i < 4; i++) {
    int pp = ty * 4 + i;
    float* row = Ssc + pp * SST;
    float s1 = row[tx], s2 = row[tx + 32];
    float mx = fmaxf(s1, s2);
    #pragma unroll
    for (int o = 16; o; o >>= 1) mx = fmaxf(mx, __shfl_xor_sync(0xffffffffu, mx, o));
    float e1 = __expf(s1 - mx), e2 = __expf(s2 - mx);
    float z = e1 + e2;
    #pragma unroll
    for (int o = 16; o; o >>= 1) z += __shfl_xor_sync(0xffffffffu, z, o);
    float a1 = e1 / z, a2 = e2 / z;

    #pragma unroll
    for (int half = 0; half < 2; half++) {
      int k = tx + half * 32;
      float s = half ? s2 : s1;
      float h0 = row[64 + k * 4 + 0], h1 = row[64 + k * 4 + 1];
      float h2 = row[64 + k * 4 + 2], h3 = row[64 + k * 4 + 3];
      float mxs = fmaxf(fmaxf(fmaxf(h0, h1), fmaxf(h2, h3)), s);
      float es = __expf(s - mxs);
      float d = es + __expf(h0 - mxs) + __expf(h1 - mxs) + __expf(h2 - mxs) + __expf(h3 - mxs);
      float av = (half ? a2 : a1) * (es / d);
      row[k] = av;                      // overwrite score with final a
    }
    #pragma unroll
    for (int q = 0; q < 6; q++) {
      int col = 320 + tx * 6 + q;
      row[col] = fmaxf(row[col], 0.f);  // relu in place
    }
  }
  __syncthreads();

  // ---- coalesced transposed stores ----
  #pragma unroll
  for (int i = 0; i < 8; i++) {          // g_a: 64 k x 32 p
    int idx = i * 256 + tid;
    int k = idx >> 5, pp = idx & 31;
    g_a[((size_t)n * Kk + k) * Pp + p0 + pp] = Ssc[pp * SST + k];
  }
  #pragma unroll
  for (int i = 0; i < 24; i++) {         // g_app: 192 ch x 32 p
    int idx = i * 256 + tid;
    int jj = idx >> 5, pp = idx & 31;
    g_app[((size_t)n * (Ll * Kk) + jj) * Pp + p0 + pp] = Ssc[pp * SST + 320 + jj];
  }
}

// ---------------- K5: region sums  sal[n,k,r]  (warp per region) -------------
__global__ void k_sal() {
  int k = blockIdx.x, n = blockIdx.y;
  int tid = threadIdx.x;
  __shared__ float M[3][Pp];
  #pragma unroll
  for (int l = 0; l < 3; l++)
    for (int i = tid; i < Pp; i += 256)
      M[l][i] = g_app[((size_t)n * (Ll * Kk) + l * Kk + k) * Pp + i];
  __syncthreads();
  int w = tid >> 5, lane = tid & 31;
  for (int r = w; r < Rr; r += 8) {
    int l = c_reg[r][0], h0 = c_reg[r][1], h1 = c_reg[r][2], w0 = c_reg[r][3], w1 = c_reg[r][4];
    int rw = w1 - w0, tot = (h1 - h0) * rw;
    float s = 0.f;
    for (int i = lane; i < tot; i += 32) {
      int hh = h0 + i / rw, ww = w0 + i % rw;
      s += M[l][hh * Ww + ww];
    }
    #pragma unroll
    for (int o = 16; o; o >>= 1) s += __shfl_xor_sync(0xffffffffu, s, o);
    if (lane == 0) g_sal[((size_t)n * Kk + k) * Rr + r] = s;
  }
}

// ---------------- K7: vlad GEMM partials + awsum -----------------------------
__global__ void k_vlad() {
  int n = blockIdx.y, chk = blockIdx.x;
  int p0base = chk * (Pp / NCH);               // 192 pixels per chunk
  __shared__ float Xs[32][132];
  __shared__ float awS[64][33];
  __shared__ float salsh[64][22];
  __shared__ unsigned char msh[8][32];
  int tid = threadIdx.x;
  int tx = tid & 15, ty = tid >> 4;
  int wid = tid >> 5;

  for (int i = tid; i < 64 * Rr; i += 256)
    salsh[i / Rr][i % Rr] = g_sal[(size_t)n * Kk * Rr + i];

  float acc[4][8] = {};
  float regsum[8] = {};
  for (int t = 0; t < 6; t++) {
    int p0 = p0base + t * 32;
    __syncthreads();
    #pragma unroll
    for (int i = 0; i < 4; i++) {
      int idx = i * 256 + tid;                 // float4 slot
      int pp = idx >> 5, c4 = idx & 31;
      float4 v = *(const float4*)(g_xn + (size_t)(n * Pp + p0 + pp) * 128 + c4 * 4);
      *(float4*)&Xs[pp][c4 * 4] = v;
    }
    if (tid < 32) {
      int p = p0 + tid;
      int h = p / Ww, w = p % Ww;
      int a, b;
      memb1(h, a, b); msh[0][tid] = a; msh[1][tid] = b;
      memb1(w, a, b); msh[2][tid] = a; msh[3][tid] = b;
      memb2(h, a, b); msh[4][tid] = a; msh[5][tid] = b;
      memb2(w, a, b); msh[6][tid] = a; msh[7][tid] = b;
    }
    __syncthreads();
    #pragma unroll
    for (int i = 0; i < 8; i++) {
      int idx = i * 256 + tid;
      int k = idx >> 5, pp = idx & 31;        // k = i*8 + wid
      float av = g_a[((size_t)n * Kk + k) * Pp + p0 + pp];
      const float* sk = &salsh[k][0];
      float wsum = sk[0];
      int r1l = msh[0][pp], r1h = msh[1][pp], c1l = msh[2][pp], c1h = msh[3][pp];
      int r2l = msh[4][pp], r2h = msh[5][pp], c2l = msh[6][pp], c2h = msh[7][pp];
      for (int ii = r1l; ii <= r1h; ii++)
        for (int jj = c1l; jj <= c1h; jj++) wsum += sk[1 + 2 * ii + jj];
      for (int ii = r2l; ii <= r2h; ii++)
        for (int jj = c2l; jj <= c2h; jj++) wsum += sk[5 + 4 * ii + jj];
      float aw = av * wsum;
      awS[k][pp] = aw;
      regsum[i] += aw;
    }
    __syncthreads();
    #pragma unroll
    for (int pp = 0; pp < 32; pp++) {
      float a0 = awS[ty * 4 + 0][pp];
      float a1 = awS[ty * 4 + 1][pp];
      float a2 = awS[ty * 4 + 2][pp];
      float a3 = awS[ty * 4 + 3][pp];
      float4 x0 = *(const float4*)&Xs[pp][tx * 8];
      float4 x1 = *(const float4*)&Xs[pp][tx * 8 + 4];
      acc[0][0] += a0 * x0.x; acc[0][1] += a0 * x0.y; acc[0][2] += a0 * x0.z; acc[0][3] += a0 * x0.w;
      acc[0][4] += a0 * x1.x; acc[0][5] += a0 * x1.y; acc[0][6] += a0 * x1.z; acc[0][7] += a0 * x1.w;
      acc[1][0] += a1 * x0.x; acc[1][1] += a1 * x0.y; acc[1][2] += a1 * x0.z; acc[1][3] += a1 * x0.w;
      acc[1][4] += a1 * x1.x; acc[1][5] += a1 * x1.y; acc[1][6] += a1 * x1.z; acc[1][7] += a1 * x1.w;
      acc[2][0] += a2 * x0.x; acc[2][1] += a2 * x0.y; acc[2][2] += a2 * x0.z; acc[2][3] += a2 * x0.w;
      acc[2][4] += a2 * x1.x; acc[2][5] += a2 * x1.y; acc[2][6] += a2 * x1.z; acc[2][7] += a2 * x1.w;
      acc[3][0] += a3 * x0.x; acc[3][1] += a3 * x0.y; acc[3][2] += a3 * x0.z; acc[3][3] += a3 * x0.w;
      acc[3][4] += a3 * x1.x; acc[3][5] += a3 * x1.y; acc[3][6] += a3 * x1.z; acc[3][7] += a3 * x1.w;
    }
  }
  float* outp = g_part + ((size_t)n * NCH + chk) * Kk * Cc;
  #pragma unroll
  for (int i = 0; i < 4; i++) {
    int k = ty * 4 + i;
    float4 v0 = make_float4(acc[i][0], acc[i][1], acc[i][2], acc[i][3]);
    float4 v1 = make_float4(acc[i][4], acc[i][5], acc[i][6], acc[i][7]);
    *(float4*)&outp[k * 128 + tx * 8]     = v0;
    *(float4*)&outp[k * 128 + tx * 8 + 4] = v1;
  }
  // awsum reduction: lanes in a warp share the same k per i
  #pragma unroll
  for (int i = 0; i < 8; i++) {
    float s = regsum[i];
    #pragma unroll
    for (int o = 16; o; o >>= 1) s += __shfl_xor_sync(0xffffffffu, s, o);
    if ((tid & 31) == 0) atomicAdd(&g_awsum[n * Kk + i * 8 + wid], s);
  }
}

// ---------------- K8: reduce partials, subtract centroid, intra-norm ---------
__global__ void k_fin1(const float* __restrict__ centroids,
                       const float* __restrict__ cw, float* __restrict__ out) {
  int k = blockIdx.x, n = blockIdx.y, c = threadIdx.x;   // 128 threads
  float s = 0.f;
  #pragma unroll
  for (int ch = 0; ch < NCH; ch++)
    s += g_part[(((size_t)n * NCH + ch) * Kk + k) * Cc + c];
  float v = s - centroids[k * 128 + c] * g_awsum[n * Kk + k];
  __shared__ float red[128];
  __shared__ float invs;
  red[c] = v * v; __syncthreads();
  for (int off = 64; off; off >>= 1) {
    if (c < off) red[c] += red[c + off];
    __syncthreads();
  }
  if (c == 0) invs = 1.0f / fmaxf(sqrtf(red[0]), 1e-12f);
  __syncthreads();
  float val = v * invs * cw[k];
  out[(size_t)n * (Kk * Cc) + k * 128 + c] = val;
  red[c] = val * val; __syncthreads();
  for (int off = 64; off; off >>= 1) {
    if (c < off) red[c] += red[c + off];
    __syncthreads();
  }
  if (c == 0) atomicAdd(&g_nrm[n], red[0]);
}

// ---------------- K9: global normalization ----------------------------------
__global__ void k_fin2(float* __restrict__ out) {
  int n = blockIdx.y;
  int i = blockIdx.x * 256 + threadIdx.x;
  float inv = 1.0f / fmaxf(sqrtf(g_nrm[n]), 1e-12f);
  out[(size_t)n * (Kk * Cc) + i] *= inv;
}

// ---------------- launcher ---------------------------------------------------
extern "C" void kernel_launch(void* const* d_in, const int* in_sizes, int n_in,
                              void* d_out, int out_size) {
  const float* x         = (const float*)d_in[0];  // [N,C,H,W]
  const float* centroids = (const float*)d_in[1];  // [K,C]
  const float* conv_w    = (const float*)d_in[2];  // [K,C]
  const float* shadow_w  = (const float*)d_in[3];  // [K*S,C]
  const float* app_w     = (const float*)d_in[4];  // [L,K,C]
  const float* clw       = (const float*)d_in[5];  // [K]
  float* out = (float*)d_out;

  int smem_gemm = 32 * SST * sizeof(float);  // 65664 B (>= As+Bs region)
  cudaFuncSetAttribute(k_gemm_epi, cudaFuncAttributeMaxDynamicSharedMemorySize, smem_gemm);

  k_norm<<<dim3(Pp / 32, Nn), 256>>>(x);
  k_wall<<<dim3((Jj * Cc + 255) / 256), 256>>>(conv_w, shadow_w, app_w);
  k_gemm_epi<<<MTOT / 32, 256, smem_gemm>>>();
  k_sal<<<dim3(Kk, Nn), 256>>>();
  k_vlad<<<dim3(NCH, Nn), 256>>>();
  k_fin1<<<dim3(Kk, Nn), 128>>>(centroids, clw, out);
  k_fin2<<<dim3(Kk * Cc / 256, Nn), 256>>>(out);
}

// round 5
// speedup vs baseline: 1.9295x; 1.4493x over previous
#include <cuda_runtime.h>
#include <math.h>
#include <stdint.h>

#define Nn 32
#define Cc 128
#define Hh 48
#define Ww 48
#define Pp 2304            // H*W
#define Kk 64
#define Ss 4
#define Ll 3
#define Rr 21
#define Jj 512             // 64 score + 256 shadow + 192 app
#define MTOT (Nn*Pp)       // 73728
#define NCH 12             // P-chunks in vlad GEMM (2304/12 = 192)

#define SST 513            // score tile smem stride (odd => conflict-free columns)

// ---------------- scratch (device globals; no allocs allowed) ----------------
__device__ float g_xn[(size_t)Nn*Pp*Cc];        // normalized x, pixel-major [n,p,c]
__device__ float g_wall[Jj*Cc];                 // stacked weights [j,c]
__device__ float g_a[(size_t)Nn*Kk*Pp];         // a * sal_pix  [n,k,p]
__device__ float g_app[(size_t)Nn*Ll*Kk*Pp];    // relu(app)    [n, l*K+k, p]
__device__ float g_sal[Nn*Kk*Rr];               // region sums  [n,k,r]
__device__ float g_awsum[Nn*Kk];
__device__ float g_part[(size_t)Nn*NCH*Kk*Cc];  // vlad partials
__device__ float g_nrm[Nn];

// membership helpers: which windows (per-dim) contain coordinate h
__device__ __forceinline__ void memb1(int h, int& lo, int& hi) {
  lo = (h >= 32) ? 1 : 0;
  hi = (h >= 16) ? 1 : 0;
}
__device__ __forceinline__ void memb2(int h, int& lo, int& hi) {
  lo = (h >= 19) ? ((h - 9) / 10) : 0;
  int m = (h + 1) / 10;
  hi = m > 3 ? 3 : m;
}

__device__ __forceinline__ float f2tf(float f) {
  uint32_t r; asm("cvt.rna.tf32.f32 %0, %1;" : "=r"(r) : "f"(f));
  return __uint_as_float(r);
}

// ---------------- K1: per-pixel L2 normalize + transpose to [n,p,c] ----------
__global__ void k_norm(const float* __restrict__ x) {
  int n = blockIdx.y, p0 = blockIdx.x * 32;
  __shared__ float Xs[128][33];
  __shared__ float inv[32];
  const float* xb = x + (size_t)n * Cc * Pp;
  int tid = threadIdx.x;
  #pragma unroll
  for (int i = 0; i < 16; i++) {
    int idx = i * 256 + tid;
    int c = idx >> 5, pp = idx & 31;
    Xs[c][pp] = xb[(size_t)c * Pp + p0 + pp];
  }
  __syncthreads();
  {
    int pp = tid >> 3, part = tid & 7;
    float s = 0.f;
    #pragma unroll
    for (int c = 0; c < 16; c++) { float v = Xs[part + c * 8][pp]; s += v * v; }
    s += __shfl_down_sync(0xffffffffu, s, 4);
    s += __shfl_down_sync(0xffffffffu, s, 2);
    s += __shfl_down_sync(0xffffffffu, s, 1);
    if (part == 0) inv[pp] = 1.0f / fmaxf(sqrtf(s), 1e-12f);
  }
  __syncthreads();
  float* xo = g_xn + (size_t)(n * Pp + p0) * Cc;
  #pragma unroll
  for (int i = 0; i < 16; i++) {
    int idx = i * 256 + tid;
    int pp = idx >> 7, c = idx & 127;
    xo[pp * 128 + c] = Xs[c][pp] * inv[pp];
  }
}

// ---------------- K2: assemble stacked weight matrix + zero accumulators -----
__global__ void k_wall(const float* __restrict__ cw, const float* __restrict__ shw,
                       const float* __restrict__ appw) {
  int idx = blockIdx.x * 256 + threadIdx.x;
  if (idx < 32) g_nrm[idx] = 0.f;
  if (idx < Nn * Kk) g_awsum[idx] = 0.f;
  if (idx >= Jj * Cc) return;
  int j = idx >> 7, c = idx & 127;
  float v;
  if (j < 64)       v = cw[j * 128 + c];
  else if (j < 320) v = shw[(j - 64) * 128 + c];
  else              v = appw[(j - 320) * 128 + c];
  g_wall[idx] = v;
}

// ---------------- K3: tf32 mma.sync GEMM + fused epilogue --------------------
// Block: 32 pixels x 512 outputs. Warp w owns j in [w*64, w*64+64).
// K processed in 4 chunks of 32. A/B staged in smem stride 36 (tf32).
#define ASTRIDE 36
#define BS_OFF (32 * ASTRIDE)                       // floats
#define SMEM_K3 ((BS_OFF + 512 * ASTRIDE) * 4)      // 78336 bytes

__global__ void __launch_bounds__(256) k_gemm_epi() {
  extern __shared__ float sm[];
  float* As = sm;                       // [32][36]
  float* Bs = sm + BS_OFF;              // [512][36]
  float* Ssc = sm;                      // [32][513] after GEMM (aliases As/Bs)

  int tid = threadIdx.x;
  int lane = tid & 31, w = tid >> 5;
  int gr = lane >> 2, gc = lane & 3;
  int m0 = blockIdx.x * 32;
  int n = m0 / Pp, p0 = m0 % Pp;

  float acc[2][8][4];
  #pragma unroll
  for (int mf = 0; mf < 2; mf++)
    #pragma unroll
    for (int nf = 0; nf < 8; nf++)
      #pragma unroll
      for (int q = 0; q < 4; q++) acc[mf][nf][q] = 0.f;

  #pragma unroll 1
  for (int kc = 0; kc < 128; kc += 32) {
    // A: 32 px x 32 k (one float4 per thread)
    {
      int pp = tid >> 3, q = tid & 7;
      float4 v = *(const float4*)(g_xn + (size_t)(n * Pp + p0 + pp) * 128 + kc + q * 4);
      float* d = As + pp * ASTRIDE + q * 4;
      d[0] = f2tf(v.x); d[1] = f2tf(v.y); d[2] = f2tf(v.z); d[3] = f2tf(v.w);
    }
    // B: 512 j x 32 k (16 float4 per thread)
    #pragma unroll
    for (int i = 0; i < 16; i++) {
      int idx = i * 256 + tid;
      int j = idx >> 3, q = idx & 7;
      float4 v = *(const float4*)(g_wall + (size_t)j * 128 + kc + q * 4);
      float* d = Bs + j * ASTRIDE + q * 4;
      d[0] = f2tf(v.x); d[1] = f2tf(v.y); d[2] = f2tf(v.z); d[3] = f2tf(v.w);
    }
    __syncthreads();
    #pragma unroll
    for (int ks = 0; ks < 4; ks++) {
      int kb = ks * 8;
      uint32_t a[2][4];
      #pragma unroll
      for (int mf = 0; mf < 2; mf++) {
        const float* ap = As + (mf * 16 + gr) * ASTRIDE + kb + gc;
        a[mf][0] = __float_as_uint(ap[0]);
        a[mf][1] = __float_as_uint(ap[8 * ASTRIDE]);
        a[mf][2] = __float_as_uint(ap[4]);
        a[mf][3] = __float_as_uint(ap[8 * ASTRIDE + 4]);
      }
      #pragma unroll
      for (int nf = 0; nf < 8; nf++) {
        const float* bp = Bs + (w * 64 + nf * 8 + gr) * ASTRIDE + kb + gc;
        uint32_t b0 = __float_as_uint(bp[0]);
        uint32_t b1 = __float_as_uint(bp[4]);
        #pragma unroll
        for (int mf = 0; mf < 2; mf++) {
          asm volatile(
            "mma.sync.aligned.m16n8k8.row.col.f32.tf32.tf32.f32 "
            "{%0,%1,%2,%3}, {%4,%5,%6,%7}, {%8,%9}, {%0,%1,%2,%3};"
            : "+f"(acc[mf][nf][0]), "+f"(acc[mf][nf][1]),
              "+f"(acc[mf][nf][2]), "+f"(acc[mf][nf][3])
            : "r"(a[mf][0]), "r"(a[mf][1]), "r"(a[mf][2]), "r"(a[mf][3]),
              "r"(b0), "r"(b1));
        }
      }
    }
    __syncthreads();
  }

  // ---- stage scores into Ssc[32][513] ----
  #pragma unroll
  for (int mf = 0; mf < 2; mf++)
    #pragma unroll
    for (int nf = 0; nf < 8; nf++) {
      int r0 = mf * 16 + gr;
      int cb = w * 64 + nf * 8 + 2 * gc;
      Ssc[r0 * SST + cb]           = acc[mf][nf][0];
      Ssc[r0 * SST + cb + 1]       = acc[mf][nf][1];
      Ssc[(r0 + 8) * SST + cb]     = acc[mf][nf][2];
      Ssc[(r0 + 8) * SST + cb + 1] = acc[mf][nf][3];
    }
  __syncthreads();

  // ---- per-pixel epilogue: warp w owns pixels w*4 .. w*4+3 ----
  int tx = lane;
  #pragma unroll
  for (int i = 0; i < 4; i++) {
    int pp = w * 4 + i;
    float* row = Ssc + pp * SST;
    float s1 = row[tx], s2 = row[tx + 32];
    float mx = fmaxf(s1, s2);
    #pragma unroll
    for (int o = 16; o; o >>= 1) mx = fmaxf(mx, __shfl_xor_sync(0xffffffffu, mx, o));
    float e1 = __expf(s1 - mx), e2 = __expf(s2 - mx);
    float z = e1 + e2;
    #pragma unroll
    for (int o = 16; o; o >>= 1) z += __shfl_xor_sync(0xffffffffu, z, o);
    float a1 = e1 / z, a2 = e2 / z;

    #pragma unroll
    for (int half = 0; half < 2; half++) {
      int k = tx + half * 32;
      float s = half ? s2 : s1;
      float h0 = row[64 + k * 4 + 0], h1 = row[64 + k * 4 + 1];
      float h2 = row[64 + k * 4 + 2], h3 = row[64 + k * 4 + 3];
      float mxs = fmaxf(fmaxf(fmaxf(h0, h1), fmaxf(h2, h3)), s);
      float es = __expf(s - mxs);
      float d = es + __expf(h0 - mxs) + __expf(h1 - mxs) + __expf(h2 - mxs) + __expf(h3 - mxs);
      float av = (half ? a2 : a1) * (es / d);
      row[k] = av;                      // overwrite score with final a
    }
    #pragma unroll
    for (int q = 0; q < 6; q++) {
      int col = 320 + tx * 6 + q;
      row[col] = fmaxf(row[col], 0.f);  // relu in place
    }
  }
  __syncthreads();

  // ---- coalesced transposed stores ----
  #pragma unroll
  for (int i = 0; i < 8; i++) {          // g_a: 64 k x 32 p
    int idx = i * 256 + tid;
    int k = idx >> 5, pp = idx & 31;
    g_a[((size_t)n * Kk + k) * Pp + p0 + pp] = Ssc[pp * SST + k];
  }
  #pragma unroll
  for (int i = 0; i < 24; i++) {         // g_app: 192 ch x 32 p
    int idx = i * 256 + tid;
    int jj = idx >> 5, pp = idx & 31;
    g_app[((size_t)n * (Ll * Kk) + jj) * Pp + p0 + pp] = Ssc[pp * SST + 320 + jj];
  }
}

// ---------------- K5: region sums  sal[n,k,r]  (mask-FMA, div-free) ---------
__global__ void k_sal() {
  int k = blockIdx.x, n = blockIdx.y;
  int tid = threadIdx.x, wid = tid >> 5, lane = tid & 31;
  const float* A0 = g_app + ((size_t)n * (Ll * Kk) + k) * Pp;
  const float* A1 = A0 + (size_t)Kk * Pp;
  const float* A2 = A0 + (size_t)(2 * Kk) * Pp;
  float acc[21];
  #pragma unroll
  for (int r = 0; r < 21; r++) acc[r] = 0.f;
  for (int p = tid; p < Pp; p += 256) {
    float v0 = A0[p], v1 = A1[p], v2 = A2[p];
    int h = p / 48, w = p - h * 48;
    acc[0] += v0;
    float vh0 = (h < 32) ? v1 : 0.f, vh1 = (h >= 16) ? v1 : 0.f;
    float w10 = (w < 32) ? 1.f : 0.f, w11 = (w >= 16) ? 1.f : 0.f;
    acc[1] += vh0 * w10; acc[2] += vh0 * w11;
    acc[3] += vh1 * w10; acc[4] += vh1 * w11;
    float u0 = (h < 19) ? v2 : 0.f;
    float u1 = (h >= 9 && h < 29) ? v2 : 0.f;
    float u2 = (h >= 19 && h < 39) ? v2 : 0.f;
    float u3 = (h >= 29) ? v2 : 0.f;
    float m0 = (w < 19) ? 1.f : 0.f;
    float m1 = (w >= 9 && w < 29) ? 1.f : 0.f;
    float m2 = (w >= 19 && w < 39) ? 1.f : 0.f;
    float m3 = (w >= 29) ? 1.f : 0.f;
    acc[5]  += u0 * m0; acc[6]  += u0 * m1; acc[7]  += u0 * m2; acc[8]  += u0 * m3;
    acc[9]  += u1 * m0; acc[10] += u1 * m1; acc[11] += u1 * m2; acc[12] += u1 * m3;
    acc[13] += u2 * m0; acc[14] += u2 * m1; acc[15] += u2 * m2; acc[16] += u2 * m3;
    acc[17] += u3 * m0; acc[18] += u3 * m1; acc[19] += u3 * m2; acc[20] += u3 * m3;
  }
  __shared__ float red[8][21];
  #pragma unroll
  for (int r = 0; r < 21; r++) {
    float s = acc[r];
    #pragma unroll
    for (int o = 16; o; o >>= 1) s += __shfl_xor_sync(0xffffffffu, s, o);
    if (lane == 0) red[wid][r] = s;
  }
  __syncthreads();
  if (tid < 21) {
    float s = 0.f;
    #pragma unroll
    for (int w = 0; w < 8; w++) s += red[w][tid];
    g_sal[((size_t)n * Kk + k) * Rr + tid] = s;
  }
}

// ---------------- K7: vlad GEMM partials + awsum -----------------------------
__global__ void k_vlad() {
  int n = blockIdx.y, chk = blockIdx.x;
  int p0base = chk * (Pp / NCH);               // 192 pixels per chunk
  __shared__ float Xs[32][132];
  __shared__ float awS[64][33];
  __shared__ float salsh[64][22];
  __shared__ unsigned char msh[8][32];
  int tid = threadIdx.x;
  int tx = tid & 15, ty = tid >> 4;
  int wid = tid >> 5;

  for (int i = tid; i < 64 * Rr; i += 256)
    salsh[i / Rr][i % Rr] = g_sal[(size_t)n * Kk * Rr + i];

  float acc[4][8] = {};
  float regsum[8] = {};
  for (int t = 0; t < 6; t++) {
    int p0 = p0base + t * 32;
    __syncthreads();
    #pragma unroll
    for (int i = 0; i < 4; i++) {
      int idx = i * 256 + tid;                 // float4 slot
      int pp = idx >> 5, c4 = idx & 31;
      float4 v = *(const float4*)(g_xn + (size_t)(n * Pp + p0 + pp) * 128 + c4 * 4);
      *(float4*)&Xs[pp][c4 * 4] = v;
    }
    if (tid < 32) {
      int p = p0 + tid;
      int h = p / Ww, w = p % Ww;
      int a, b;
      memb1(h, a, b); msh[0][tid] = a; msh[1][tid] = b;
      memb1(w, a, b); msh[2][tid] = a; msh[3][tid] = b;
      memb2(h, a, b); msh[4][tid] = a; msh[5][tid] = b;
      memb2(w, a, b); msh[6][tid] = a; msh[7][tid] = b;
    }
    __syncthreads();
    #pragma unroll
    for (int i = 0; i < 8; i++) {
      int idx = i * 256 + tid;
      int k = idx >> 5, pp = idx & 31;        // k = i*8 + wid
      float av = g_a[((size_t)n * Kk + k) * Pp + p0 + pp];
      const float* sk = &salsh[k][0];
      float wsum = sk[0];
      int r1l = msh[0][pp], r1h = msh[1][pp], c1l = msh[2][pp], c1h = msh[3][pp];
      int r2l = msh[4][pp], r2h = msh[5][pp], c2l = msh[6][pp], c2h = msh[7][pp];
      for (int ii = r1l; ii <= r1h; ii++)
        for (int jj = c1l; jj <= c1h; jj++) wsum += sk[1 + 2 * ii + jj];
      for (int ii = r2l; ii <= r2h; ii++)
        for (int jj = c2l; jj <= c2h; jj++) wsum += sk[5 + 4 * ii + jj];
      float aw = av * wsum;
      awS[k][pp] = aw;
      regsum[i] += aw;
    }
    __syncthreads();
    #pragma unroll
    for (int pp = 0; pp < 32; pp++) {
      float a0 = awS[ty * 4 + 0][pp];
      float a1 = awS[ty * 4 + 1][pp];
      float a2 = awS[ty * 4 + 2][pp];
      float a3 = awS[ty * 4 + 3][pp];
      float4 x0 = *(const float4*)&Xs[pp][tx * 8];
      float4 x1 = *(const float4*)&Xs[pp][tx * 8 + 4];
      acc[0][0] += a0 * x0.x; acc[0][1] += a0 * x0.y; acc[0][2] += a0 * x0.z; acc[0][3] += a0 * x0.w;
      acc[0][4] += a0 * x1.x; acc[0][5] += a0 * x1.y; acc[0][6] += a0 * x1.z; acc[0][7] += a0 * x1.w;
      acc[1][0] += a1 * x0.x; acc[1][1] += a1 * x0.y; acc[1][2] += a1 * x0.z; acc[1][3] += a1 * x0.w;
      acc[1][4] += a1 * x1.x; acc[1][5] += a1 * x1.y; acc[1][6] += a1 * x1.z; acc[1][7] += a1 * x1.w;
      acc[2][0] += a2 * x0.x; acc[2][1] += a2 * x0.y; acc[2][2] += a2 * x0.z; acc[2][3] += a2 * x0.w;
      acc[2][4] += a2 * x1.x; acc[2][5] += a2 * x1.y; acc[2][6] += a2 * x1.z; acc[2][7] += a2 * x1.w;
      acc[3][0] += a3 * x0.x; acc[3][1] += a3 * x0.y; acc[3][2] += a3 * x0.z; acc[3][3] += a3 * x0.w;
      acc[3][4] += a3 * x1.x; acc[3][5] += a3 * x1.y; acc[3][6] += a3 * x1.z; acc[3][7] += a3 * x1.w;
    }
  }
  float* outp = g_part + ((size_t)n * NCH + chk) * Kk * Cc;
  #pragma unroll
  for (int i = 0; i < 4; i++) {
    int k = ty * 4 + i;
    float4 v0 = make_float4(acc[i][0], acc[i][1], acc[i][2], acc[i][3]);
    float4 v1 = make_float4(acc[i][4], acc[i][5], acc[i][6], acc[i][7]);
    *(float4*)&outp[k * 128 + tx * 8]     = v0;
    *(float4*)&outp[k * 128 + tx * 8 + 4] = v1;
  }
  #pragma unroll
  for (int i = 0; i < 8; i++) {
    float s = regsum[i];
    #pragma unroll
    for (int o = 16; o; o >>= 1) s += __shfl_xor_sync(0xffffffffu, s, o);
    if ((tid & 31) == 0) atomicAdd(&g_awsum[n * Kk + i * 8 + wid], s);
  }
}

// ---------------- K8: reduce partials, subtract centroid, intra-norm ---------
__global__ void k_fin1(const float* __restrict__ centroids,
                       const float* __restrict__ cw, float* __restrict__ out) {
  int k = blockIdx.x, n = blockIdx.y, c = threadIdx.x;   // 128 threads
  float s = 0.f;
  #pragma unroll
  for (int ch = 0; ch < NCH; ch++)
    s += g_part[(((size_t)n * NCH + ch) * Kk + k) * Cc + c];
  float v = s - centroids[k * 128 + c] * g_awsum[n * Kk + k];
  __shared__ float red[128];
  __shared__ float invs;
  red[c] = v * v; __syncthreads();
  for (int off = 64; off; off >>= 1) {
    if (c < off) red[c] += red[c + off];
    __syncthreads();
  }
  if (c == 0) invs = 1.0f / fmaxf(sqrtf(red[0]), 1e-12f);
  __syncthreads();
  float val = v * invs * cw[k];
  out[(size_t)n * (Kk * Cc) + k * 128 + c] = val;
  red[c] = val * val; __syncthreads();
  for (int off = 64; off; off >>= 1) {
    if (c < off) red[c] += red[c + off];
    __syncthreads();
  }
  if (c == 0) atomicAdd(&g_nrm[n], red[0]);
}

// ---------------- K9: global normalization ----------------------------------
__global__ void k_fin2(float* __restrict__ out) {
  int n = blockIdx.y;
  int i = blockIdx.x * 256 + threadIdx.x;
  float inv = 1.0f / fmaxf(sqrtf(g_nrm[n]), 1e-12f);
  out[(size_t)n * (Kk * Cc) + i] *= inv;
}

// ---------------- launcher ---------------------------------------------------
extern "C" void kernel_launch(void* const* d_in, const int* in_sizes, int n_in,
                              void* d_out, int out_size) {
  const float* x         = (const float*)d_in[0];  // [N,C,H,W]
  const float* centroids = (const float*)d_in[1];  // [K,C]
  const float* conv_w    = (const float*)d_in[2];  // [K,C]
  const float* shadow_w  = (const float*)d_in[3];  // [K*S,C]
  const float* app_w     = (const float*)d_in[4];  // [L,K,C]
  const float* clw       = (const float*)d_in[5];  // [K]
  float* out = (float*)d_out;

  cudaFuncSetAttribute(k_gemm_epi, cudaFuncAttributeMaxDynamicSharedMemorySize, SMEM_K3);

  k_norm<<<dim3(Pp / 32, Nn), 256>>>(x);
  k_wall<<<dim3((Jj * Cc + 255) / 256), 256>>>(conv_w, shadow_w, app_w);
  k_gemm_epi<<<MTOT / 32, 256, SMEM_K3>>>();
  k_sal<<<dim3(Kk, Nn), 256>>>();
  k_vlad<<<dim3(NCH, Nn), 256>>>();
  k_fin1<<<dim3(Kk, Nn), 128>>>(centroids, clw, out);
  k_fin2<<<dim3(Kk * Cc / 256, Nn), 256>>>(out);
}

// round 6
// speedup vs baseline: 2.1519x; 1.1152x over previous
#include <cuda_runtime.h>
#include <math.h>
#include <stdint.h>

#define Nn 32
#define Cc 128
#define Hh 48
#define Ww 48
#define Pp 2304            // H*W
#define Kk 64
#define Ss 4
#define Ll 3
#define Rr 21
#define Jj 512             // 64 score + 256 shadow + 192 app
#define MTOT (Nn*Pp)       // 73728
#define NCH 12             // P-chunks in vlad GEMM (2304/12 = 192)

#define SST 513            // score tile smem stride

// ---------------- scratch (device globals; no allocs allowed) ----------------
__device__ float g_xn[(size_t)Nn*Pp*Cc];        // normalized x, pixel-major [n,p,c]
__device__ float g_inv[(size_t)Nn*Pp];          // 1/norm per pixel
__device__ float g_wall[Jj*Cc];                 // stacked weights [j,c]
__device__ float g_a[(size_t)Nn*Kk*Pp];         // a * sal_pix  [n,k,p]
__device__ float g_app[(size_t)Nn*Ll*Kk*Pp];    // relu(app)    [n, l*K+k, p]
__device__ float g_sal[Nn*Kk*Rr];               // region sums  [n,k,r]
__device__ float g_awsum[Nn*Kk];
__device__ float g_part[(size_t)Nn*NCH*Kk*Cc];  // vlad partials
__device__ float g_nrm[Nn];

// membership helpers: which windows (per-dim) contain coordinate h
__device__ __forceinline__ void memb1(int h, int& lo, int& hi) {
  lo = (h >= 32) ? 1 : 0;
  hi = (h >= 16) ? 1 : 0;
}
__device__ __forceinline__ void memb2(int h, int& lo, int& hi) {
  lo = (h >= 19) ? ((h - 9) / 10) : 0;
  int m = (h + 1) / 10;
  hi = m > 3 ? 3 : m;
}

__device__ __forceinline__ float f2tf(float f) {
  uint32_t r; asm("cvt.rna.tf32.f32 %0, %1;" : "=r"(r) : "f"(f));
  return __uint_as_float(r);
}
#define MMA_TF32(acc, a0, a1, a2, a3, b0, b1) \
  asm volatile( \
    "mma.sync.aligned.m16n8k8.row.col.f32.tf32.tf32.f32 " \
    "{%0,%1,%2,%3}, {%4,%5,%6,%7}, {%8,%9}, {%0,%1,%2,%3};" \
    : "+f"((acc)[0]), "+f"((acc)[1]), "+f"((acc)[2]), "+f"((acc)[3]) \
    : "r"(a0), "r"(a1), "r"(a2), "r"(a3), "r"(b0), "r"(b1))

// ---------------- K1: per-pixel L2 normalize + transpose to [n,p,c] ----------
__global__ void k_norm(const float* __restrict__ x) {
  int n = blockIdx.y, p0 = blockIdx.x * 32;
  __shared__ float Xs[128][33];
  __shared__ float inv[32];
  const float* xb = x + (size_t)n * Cc * Pp;
  int tid = threadIdx.x;
  #pragma unroll
  for (int i = 0; i < 16; i++) {
    int idx = i * 256 + tid;
    int c = idx >> 5, pp = idx & 31;
    Xs[c][pp] = xb[(size_t)c * Pp + p0 + pp];
  }
  __syncthreads();
  {
    int pp = tid >> 3, part = tid & 7;
    float s = 0.f;
    #pragma unroll
    for (int c = 0; c < 16; c++) { float v = Xs[part + c * 8][pp]; s += v * v; }
    s += __shfl_down_sync(0xffffffffu, s, 4);
    s += __shfl_down_sync(0xffffffffu, s, 2);
    s += __shfl_down_sync(0xffffffffu, s, 1);
    if (part == 0) inv[pp] = 1.0f / fmaxf(sqrtf(s), 1e-12f);
  }
  __syncthreads();
  if (tid < 32) g_inv[(size_t)n * Pp + p0 + tid] = inv[tid];
  float* xo = g_xn + (size_t)(n * Pp + p0) * Cc;
  #pragma unroll
  for (int i = 0; i < 16; i++) {
    int idx = i * 256 + tid;
    int pp = idx >> 7, c = idx & 127;
    xo[pp * 128 + c] = Xs[c][pp] * inv[pp];
  }
}

// ---------------- K2: assemble stacked weight matrix + zero accumulators -----
__global__ void k_wall(const float* __restrict__ cw, const float* __restrict__ shw,
                       const float* __restrict__ appw) {
  int idx = blockIdx.x * 256 + threadIdx.x;
  if (idx < 32) g_nrm[idx] = 0.f;
  if (idx < Nn * Kk) g_awsum[idx] = 0.f;
  if (idx >= Jj * Cc) return;
  int j = idx >> 7, c = idx & 127;
  float v;
  if (j < 64)       v = cw[j * 128 + c];
  else if (j < 320) v = shw[(j - 64) * 128 + c];
  else              v = appw[(j - 320) * 128 + c];
  g_wall[idx] = v;
}

// ---------------- K3: tf32 mma.sync GEMM + fused epilogue --------------------
// Block: 64 pixels x 512 outputs, 512 threads (16 warps).
// Warp w: m-half (w&1)*32 pixels, j-range (w>>1)*64.
#define ASTRIDE 36
#define BS_OFF (64 * ASTRIDE)                     // floats
#define SMEM_K3 (64 * SST * 4)                    // 131328 B (Ssc is the max)

__global__ void __launch_bounds__(512) k_gemm_epi() {
  extern __shared__ float sm[];
  float* As = sm;                       // [64][36]
  float* Bs = sm + BS_OFF;              // [512][36]
  float* Ssc = sm;                      // [64][513] after GEMM (aliases As/Bs)

  int tid = threadIdx.x;
  int lane = tid & 31, w = tid >> 5;
  int gr = lane >> 2, gc = lane & 3;
  int mh = (w & 1) * 32;                // pixel half base
  int jb = (w >> 1) * 64;               // j range base
  int m0 = blockIdx.x * 64;
  int n = m0 / Pp, p0 = m0 % Pp;

  float acc[2][8][4];
  #pragma unroll
  for (int mf = 0; mf < 2; mf++)
    #pragma unroll
    for (int nf = 0; nf < 8; nf++)
      #pragma unroll
      for (int q = 0; q < 4; q++) acc[mf][nf][q] = 0.f;

  #pragma unroll 1
  for (int kc = 0; kc < 128; kc += 32) {
    // A: 64 px x 32 k (one float4 per thread)
    {
      int pp = tid >> 3, q = tid & 7;
      float4 v = *(const float4*)(g_xn + (size_t)(n * Pp + p0 + pp) * 128 + kc + q * 4);
      float* d = As + pp * ASTRIDE + q * 4;
      d[0] = f2tf(v.x); d[1] = f2tf(v.y); d[2] = f2tf(v.z); d[3] = f2tf(v.w);
    }
    // B: 512 j x 32 k (8 float4 per thread)
    #pragma unroll
    for (int i = 0; i < 8; i++) {
      int idx = i * 512 + tid;
      int j = idx >> 3, q = idx & 7;
      float4 v = *(const float4*)(g_wall + (size_t)j * 128 + kc + q * 4);
      float* d = Bs + j * ASTRIDE + q * 4;
      d[0] = f2tf(v.x); d[1] = f2tf(v.y); d[2] = f2tf(v.z); d[3] = f2tf(v.w);
    }
    __syncthreads();
    #pragma unroll
    for (int ks = 0; ks < 4; ks++) {
      int kb = ks * 8;
      uint32_t a[2][4];
      #pragma unroll
      for (int mf = 0; mf < 2; mf++) {
        const float* ap = As + (mh + mf * 16 + gr) * ASTRIDE + kb + gc;
        a[mf][0] = __float_as_uint(ap[0]);
        a[mf][1] = __float_as_uint(ap[8 * ASTRIDE]);
        a[mf][2] = __float_as_uint(ap[4]);
        a[mf][3] = __float_as_uint(ap[8 * ASTRIDE + 4]);
      }
      #pragma unroll
      for (int nf = 0; nf < 8; nf++) {
        const float* bp = Bs + (jb + nf * 8 + gr) * ASTRIDE + kb + gc;
        uint32_t b0 = __float_as_uint(bp[0]);
        uint32_t b1 = __float_as_uint(bp[4]);
        #pragma unroll
        for (int mf = 0; mf < 2; mf++)
          MMA_TF32(acc[mf][nf], a[mf][0], a[mf][1], a[mf][2], a[mf][3], b0, b1);
      }
    }
    __syncthreads();
  }

  // ---- stage scores into Ssc[64][513] ----
  #pragma unroll
  for (int mf = 0; mf < 2; mf++)
    #pragma unroll
    for (int nf = 0; nf < 8; nf++) {
      int r0 = mh + mf * 16 + gr;
      int cb = jb + nf * 8 + 2 * gc;
      Ssc[r0 * SST + cb]           = acc[mf][nf][0];
      Ssc[r0 * SST + cb + 1]       = acc[mf][nf][1];
      Ssc[(r0 + 8) * SST + cb]     = acc[mf][nf][2];
      Ssc[(r0 + 8) * SST + cb + 1] = acc[mf][nf][3];
    }
  __syncthreads();

  // ---- per-pixel epilogue: warp w owns pixels w*4 .. w*4+3 ----
  int tx = lane;
  #pragma unroll
  for (int i = 0; i < 4; i++) {
    int pp = w * 4 + i;
    float* row = Ssc + pp * SST;
    float s1 = row[tx], s2 = row[tx + 32];
    float mx = fmaxf(s1, s2);
    #pragma unroll
    for (int o = 16; o; o >>= 1) mx = fmaxf(mx, __shfl_xor_sync(0xffffffffu, mx, o));
    float e1 = __expf(s1 - mx), e2 = __expf(s2 - mx);
    float z = e1 + e2;
    #pragma unroll
    for (int o = 16; o; o >>= 1) z += __shfl_xor_sync(0xffffffffu, z, o);
    float a1 = e1 / z, a2 = e2 / z;

    #pragma unroll
    for (int half = 0; half < 2; half++) {
      int k = tx + half * 32;
      float s = half ? s2 : s1;
      float h0 = row[64 + k * 4 + 0], h1 = row[64 + k * 4 + 1];
      float h2 = row[64 + k * 4 + 2], h3 = row[64 + k * 4 + 3];
      float mxs = fmaxf(fmaxf(fmaxf(h0, h1), fmaxf(h2, h3)), s);
      float es = __expf(s - mxs);
      float d = es + __expf(h0 - mxs) + __expf(h1 - mxs) + __expf(h2 - mxs) + __expf(h3 - mxs);
      float av = (half ? a2 : a1) * (es / d);
      row[k] = av;                      // overwrite score with final a
    }
    #pragma unroll
    for (int q = 0; q < 6; q++) {
      int col = 320 + tx * 6 + q;
      row[col] = fmaxf(row[col], 0.f);  // relu in place
    }
  }
  __syncthreads();

  // ---- coalesced transposed stores ----
  #pragma unroll
  for (int i = 0; i < 8; i++) {          // g_a: 64 k x 64 p
    int idx = i * 512 + tid;
    int k = idx >> 6, pp = idx & 63;
    g_a[((size_t)n * Kk + k) * Pp + p0 + pp] = Ssc[pp * SST + k];
  }
  #pragma unroll
  for (int i = 0; i < 24; i++) {         // g_app: 192 ch x 64 p
    int idx = i * 512 + tid;
    int jj = idx >> 6, pp = idx & 63;
    g_app[((size_t)n * (Ll * Kk) + jj) * Pp + p0 + pp] = Ssc[pp * SST + 320 + jj];
  }
}

// ---------------- K5: region sums  sal[n,k,r]  (mask-FMA, div-free) ---------
__global__ void k_sal() {
  int k = blockIdx.x, n = blockIdx.y;
  int tid = threadIdx.x, wid = tid >> 5, lane = tid & 31;
  const float* A0 = g_app + ((size_t)n * (Ll * Kk) + k) * Pp;
  const float* A1 = A0 + (size_t)Kk * Pp;
  const float* A2 = A0 + (size_t)(2 * Kk) * Pp;
  float acc[21];
  #pragma unroll
  for (int r = 0; r < 21; r++) acc[r] = 0.f;
  int h = tid / 48, ww = tid - h * 48;
  for (int p = tid; p < Pp; p += 256) {
    float v0 = A0[p], v1 = A1[p], v2 = A2[p];
    acc[0] += v0;
    float vh0 = (h < 32) ? v1 : 0.f, vh1 = (h >= 16) ? v1 : 0.f;
    float w10 = (ww < 32) ? 1.f : 0.f, w11 = (ww >= 16) ? 1.f : 0.f;
    acc[1] += vh0 * w10; acc[2] += vh0 * w11;
    acc[3] += vh1 * w10; acc[4] += vh1 * w11;
    float u0 = (h < 19) ? v2 : 0.f;
    float u1 = (h >= 9 && h < 29) ? v2 : 0.f;
    float u2 = (h >= 19 && h < 39) ? v2 : 0.f;
    float u3 = (h >= 29) ? v2 : 0.f;
    float m0 = (ww < 19) ? 1.f : 0.f;
    float m1 = (ww >= 9 && ww < 29) ? 1.f : 0.f;
    float m2 = (ww >= 19 && ww < 39) ? 1.f : 0.f;
    float m3 = (ww >= 29) ? 1.f : 0.f;
    acc[5]  += u0 * m0; acc[6]  += u0 * m1; acc[7]  += u0 * m2; acc[8]  += u0 * m3;
    acc[9]  += u1 * m0; acc[10] += u1 * m1; acc[11] += u1 * m2; acc[12] += u1 * m3;
    acc[13] += u2 * m0; acc[14] += u2 * m1; acc[15] += u2 * m2; acc[16] += u2 * m3;
    acc[17] += u3 * m0; acc[18] += u3 * m1; acc[19] += u3 * m2; acc[20] += u3 * m3;
    ww += 16; h += 5;
    if (ww >= 48) { ww -= 48; h += 1; }
  }
  __shared__ float red[8][21];
  #pragma unroll
  for (int r = 0; r < 21; r++) {
    float s = acc[r];
    #pragma unroll
    for (int o = 16; o; o >>= 1) s += __shfl_xor_sync(0xffffffffu, s, o);
    if (lane == 0) red[wid][r] = s;
  }
  __syncthreads();
  if (tid < 21) {
    float s = 0.f;
    #pragma unroll
    for (int w = 0; w < 8; w++) s += red[w][tid];
    g_sal[((size_t)n * Kk + k) * Rr + tid] = s;
  }
}

// ---------------- K7: vlad via tf32 mma.sync (split-B) + awsum --------------
// Block (n, chk): part[64 k][128 c] += aw[64, 192p] x xn[192p, 128c]
// A = aw (tf32), B = xn as [c][p] from raw x * inv (hi+lo split).
#define VSAL_OFF 0
#define VA_OFF   (64 * 22)                 // 1408
#define VBH_OFF  (VA_OFF + 64 * 36)        // 3712
#define VBL_OFF  (VBH_OFF + 128 * 36)      // 8320
#define SMEM_V   ((VBL_OFF + 128 * 36) * 4)  // 51712 B

__global__ void __launch_bounds__(256) k_vlad(const float* __restrict__ x) {
  extern __shared__ float sm[];
  float* salsh = sm + VSAL_OFF;          // [64][22]
  float* As    = sm + VA_OFF;            // [64][36]  aw tf32
  float* Bh    = sm + VBH_OFF;           // [128][36] xn hi tf32
  float* Bl    = sm + VBL_OFF;           // [128][36] xn lo tf32
  __shared__ unsigned char msh[8][32];
  __shared__ float iv[32];

  int tid = threadIdx.x, lane = tid & 31, w = tid >> 5;
  int gr = lane >> 2, gc = lane & 3;
  int n = blockIdx.y, chk = blockIdx.x;
  int p0base = chk * (Pp / NCH);

  for (int i = tid; i < 64 * 21; i += 256)
    salsh[(i / 21) * 22 + (i % 21)] = g_sal[(size_t)n * Kk * Rr + i];

  float acc[8][4];
  #pragma unroll
  for (int nf = 0; nf < 8; nf++)
    #pragma unroll
    for (int q = 0; q < 4; q++) acc[nf][q] = 0.f;
  float regsum[8] = {};

  #pragma unroll 1
  for (int t = 0; t < 6; t++) {
    int p0 = p0base + t * 32;
    __syncthreads();                      // prior mma reads done
    if (tid < 32) {
      int p = p0 + tid;
      iv[tid] = g_inv[(size_t)n * Pp + p];
      int h = p / Ww, wq = p % Ww;
      int a, b;
      memb1(h, a, b);  msh[0][tid] = a; msh[1][tid] = b;
      memb1(wq, a, b); msh[2][tid] = a; msh[3][tid] = b;
      memb2(h, a, b);  msh[4][tid] = a; msh[5][tid] = b;
      memb2(wq, a, b); msh[6][tid] = a; msh[7][tid] = b;
    }
    __syncthreads();
    // B tiles: [c][pp] from raw x (channel-major, p-contiguous => coalesced)
    #pragma unroll
    for (int i = 0; i < 4; i++) {
      int idx = i * 256 + tid;
      int c = idx >> 3, q = idx & 7;
      float4 v = *(const float4*)(x + ((size_t)n * Cc + c) * Pp + p0 + q * 4);
      float x0 = v.x * iv[q * 4 + 0], x1 = v.y * iv[q * 4 + 1];
      float x2 = v.z * iv[q * 4 + 2], x3 = v.w * iv[q * 4 + 3];
      float h0 = f2tf(x0), h1 = f2tf(x1), h2 = f2tf(x2), h3 = f2tf(x3);
      *(float4*)(Bh + c * 36 + q * 4) = make_float4(h0, h1, h2, h3);
      *(float4*)(Bl + c * 36 + q * 4) =
          make_float4(f2tf(x0 - h0), f2tf(x1 - h1), f2tf(x2 - h2), f2tf(x3 - h3));
    }
    // aw tile: k = i*8 + w, pp = lane
    #pragma unroll
    for (int i = 0; i < 8; i++) {
      int k = i * 8 + w;
      float av = g_a[((size_t)n * Kk + k) * Pp + p0 + lane];
      const float* sk = salsh + k * 22;
      float wsum = sk[0];
      int r1l = msh[0][lane], r1h = msh[1][lane], c1l = msh[2][lane], c1h = msh[3][lane];
      int r2l = msh[4][lane], r2h = msh[5][lane], c2l = msh[6][lane], c2h = msh[7][lane];
      for (int ii = r1l; ii <= r1h; ii++)
        for (int jj = c1l; jj <= c1h; jj++) wsum += sk[1 + 2 * ii + jj];
      for (int ii = r2l; ii <= r2h; ii++)
        for (int jj = c2l; jj <= c2h; jj++) wsum += sk[5 + 4 * ii + jj];
      float aw = f2tf(av * wsum);          // tf32 value used in BOTH mma and awsum
      As[k * 36 + lane] = aw;
      regsum[i] += aw;
    }
    __syncthreads();
    // mma: warp w -> m-frag (w>>1) [16 k], c-half (w&1) [64 c]
    #pragma unroll
    for (int ks = 0; ks < 4; ks++) {
      int kb = ks * 8;
      const float* ap = As + ((w >> 1) * 16 + gr) * 36 + kb + gc;
      uint32_t a0 = __float_as_uint(ap[0]);
      uint32_t a1 = __float_as_uint(ap[8 * 36]);
      uint32_t a2 = __float_as_uint(ap[4]);
      uint32_t a3 = __float_as_uint(ap[8 * 36 + 4]);
      #pragma unroll
      for (int nf = 0; nf < 8; nf++) {
        int crow = (w & 1) * 64 + nf * 8 + gr;
        const float* bph = Bh + crow * 36 + kb + gc;
        const float* bpl = Bl + crow * 36 + kb + gc;
        MMA_TF32(acc[nf], a0, a1, a2, a3,
                 __float_as_uint(bph[0]), __float_as_uint(bph[4]));
        MMA_TF32(acc[nf], a0, a1, a2, a3,
                 __float_as_uint(bpl[0]), __float_as_uint(bpl[4]));
      }
    }
  }

  // ---- store partials ----
  float* outp = g_part + ((size_t)n * NCH + chk) * Kk * Cc;
  #pragma unroll
  for (int nf = 0; nf < 8; nf++) {
    int r = (w >> 1) * 16 + gr;
    int col = (w & 1) * 64 + nf * 8 + 2 * gc;
    outp[r * 128 + col]           = acc[nf][0];
    outp[r * 128 + col + 1]       = acc[nf][1];
    outp[(r + 8) * 128 + col]     = acc[nf][2];
    outp[(r + 8) * 128 + col + 1] = acc[nf][3];
  }
  // ---- awsum: lanes of warp w share k = i*8 + w ----
  #pragma unroll
  for (int i = 0; i < 8; i++) {
    float s = regsum[i];
    #pragma unroll
    for (int o = 16; o; o >>= 1) s += __shfl_xor_sync(0xffffffffu, s, o);
    if (lane == 0) atomicAdd(&g_awsum[n * Kk + i * 8 + w], s);
  }
}

// ---------------- K8: reduce partials, subtract centroid, intra-norm ---------
__global__ void k_fin1(const float* __restrict__ centroids,
                       const float* __restrict__ cw, float* __restrict__ out) {
  int k = blockIdx.x, n = blockIdx.y, c = threadIdx.x;   // 128 threads
  float s = 0.f;
  #pragma unroll
  for (int ch = 0; ch < NCH; ch++)
    s += g_part[(((size_t)n * NCH + ch) * Kk + k) * Cc + c];
  float v = s - centroids[k * 128 + c] * g_awsum[n * Kk + k];
  __shared__ float red[128];
  __shared__ float invs;
  red[c] = v * v; __syncthreads();
  for (int off = 64; off; off >>= 1) {
    if (c < off) red[c] += red[c + off];
    __syncthreads();
  }
  if (c == 0) invs = 1.0f / fmaxf(sqrtf(red[0]), 1e-12f);
  __syncthreads();
  float val = v * invs * cw[k];
  out[(size_t)n * (Kk * Cc) + k * 128 + c] = val;
  red[c] = val * val; __syncthreads();
  for (int off = 64; off; off >>= 1) {
    if (c < off) red[c] += red[c + off];
    __syncthreads();
  }
  if (c == 0) atomicAdd(&g_nrm[n], red[0]);
}

// ---------------- K9: global normalization ----------------------------------
__global__ void k_fin2(float* __restrict__ out) {
  int n = blockIdx.y;
  int i = blockIdx.x * 256 + threadIdx.x;
  float inv = 1.0f / fmaxf(sqrtf(g_nrm[n]), 1e-12f);
  out[(size_t)n * (Kk * Cc) + i] *= inv;
}

// ---------------- launcher ---------------------------------------------------
extern "C" void kernel_launch(void* const* d_in, const int* in_sizes, int n_in,
                              void* d_out, int out_size) {
  const float* x         = (const float*)d_in[0];  // [N,C,H,W]
  const float* centroids = (const float*)d_in[1];  // [K,C]
  const float* conv_w    = (const float*)d_in[2];  // [K,C]
  const float* shadow_w  = (const float*)d_in[3];  // [K*S,C]
  const float* app_w     = (const float*)d_in[4];  // [L,K,C]
  const float* clw       = (const float*)d_in[5];  // [K]
  float* out = (float*)d_out;

  cudaFuncSetAttribute(k_gemm_epi, cudaFuncAttributeMaxDynamicSharedMemorySize, SMEM_K3);
  cudaFuncSetAttribute(k_vlad, cudaFuncAttributeMaxDynamicSharedMemorySize, SMEM_V);

  k_norm<<<dim3(Pp / 32, Nn), 256>>>(x);
  k_wall<<<dim3((Jj * Cc + 255) / 256), 256>>>(conv_w, shadow_w, app_w);
  k_gemm_epi<<<MTOT / 64, 512, SMEM_K3>>>();
  k_sal<<<dim3(Kk, Nn), 256>>>();
  k_vlad<<<dim3(NCH, Nn), 256, SMEM_V>>>(x);
  k_fin1<<<dim3(Kk, Nn), 128>>>(centroids, clw, out);
  k_fin2<<<dim3(Kk * Cc / 256, Nn), 256>>>(out);
}

// round 7
// speedup vs baseline: 2.3053x; 1.0713x over previous
#include <cuda_runtime.h>
#include <math.h>
#include <stdint.h>

#define Nn 32
#define Cc 128
#define Hh 48
#define Ww 48
#define Pp 2304            // H*W
#define Kk 64
#define Ss 4
#define Ll 3
#define Rr 21
#define Jj 512             // 64 score + 256 shadow + 192 app
#define MTOT (Nn*Pp)       // 73728
#define NCH 12             // P-chunks in vlad GEMM (2304/12 = 192)

#define SST 513            // score tile smem stride

// ---------------- scratch (device globals; no allocs allowed) ----------------
__device__ float g_inv[(size_t)Nn*Pp];          // 1/norm per pixel
__device__ float g_wall[Jj*Cc];                 // stacked weights [j,c]
__device__ float g_a[(size_t)Nn*Kk*Pp];         // a * sal_pix  [n,k,p]
__device__ float g_sal[Nn*Kk*Rr];               // region sums  [n,k,r]
__device__ float g_awsum[Nn*Kk];
__device__ float g_part[(size_t)Nn*NCH*Kk*Cc];  // vlad partials
__device__ float g_nrm[Nn];

// membership helpers: which windows (per-dim) contain coordinate h
__device__ __forceinline__ void memb1(int h, int& lo, int& hi) {
  lo = (h >= 32) ? 1 : 0;
  hi = (h >= 16) ? 1 : 0;
}
__device__ __forceinline__ void memb2(int h, int& lo, int& hi) {
  lo = (h >= 19) ? ((h - 9) / 10) : 0;
  int m = (h + 1) / 10;
  hi = m > 3 ? 3 : m;
}

__device__ __forceinline__ float f2tf(float f) {
  uint32_t r; asm("cvt.rna.tf32.f32 %0, %1;" : "=r"(r) : "f"(f));
  return __uint_as_float(r);
}
#define MMA_TF32(acc, a0, a1, a2, a3, b0, b1) \
  asm volatile( \
    "mma.sync.aligned.m16n8k8.row.col.f32.tf32.tf32.f32 " \
    "{%0,%1,%2,%3}, {%4,%5,%6,%7}, {%8,%9}, {%0,%1,%2,%3};" \
    : "+f"((acc)[0]), "+f"((acc)[1]), "+f"((acc)[2]), "+f"((acc)[3]) \
    : "r"(a0), "r"(a1), "r"(a2), "r"(a3), "r"(b0), "r"(b1))

// ---------------- K2: assemble stacked weight matrix + zero accumulators -----
__global__ void k_wall(const float* __restrict__ cw, const float* __restrict__ shw,
                       const float* __restrict__ appw) {
  int idx = blockIdx.x * 256 + threadIdx.x;
  if (idx < 32) g_nrm[idx] = 0.f;
  if (idx < Nn * Kk) g_awsum[idx] = 0.f;
  if (idx < Nn * Kk * Rr) g_sal[idx] = 0.f;
  if (idx >= Jj * Cc) return;
  int j = idx >> 7, c = idx & 127;
  float v;
  if (j < 64)       v = cw[j * 128 + c];
  else if (j < 320) v = shw[(j - 64) * 128 + c];
  else              v = appw[(j - 320) * 128 + c];
  g_wall[idx] = v;
}

// ---------------- K3: norm + tf32 GEMM + softmax/shadow + region sums --------
// Block: 64 pixels x 512 outputs, 512 threads.
// A [64][132] raw x -> normalized tf32 in place. B [512][36] per 32-k chunk.
#define ASA 132
#define BS_OFF (64 * ASA)                         // floats (8448)
#define SMEM_K3 (64 * SST * 4)                    // 131328 B (Ssc region is max)

__global__ void __launch_bounds__(512) k_gemm_epi(const float* __restrict__ x) {
  extern __shared__ float sm[];
  float* As = sm;                       // [64][132]
  float* Bs = sm + BS_OFF;              // [512][36]
  float* Ssc = sm;                      // [64][513] after GEMM (aliases As/Bs)
  __shared__ float inv_s[64];
  __shared__ float msk[64][12];         // mh1[2], mw1[2], mh2[4], mw2[4]

  int tid = threadIdx.x;
  int lane = tid & 31, w = tid >> 5;
  int gr = lane >> 2, gc = lane & 3;
  int mh = (w & 1) * 32;                // pixel half base for GEMM
  int jb = (w >> 1) * 64;               // j range base
  int n = blockIdx.x / 36, p0 = (blockIdx.x % 36) * 64;

  // ---- Phase A: load raw x [64 px][128 c] transposed into As ----
  #pragma unroll
  for (int i = 0; i < 4; i++) {
    int idx = i * 512 + tid;            // 2048 float4 slots
    int c = idx >> 4, q = idx & 15;
    float4 v = *(const float4*)(x + ((size_t)n * Cc + c) * Pp + p0 + q * 4);
    As[(q * 4 + 0) * ASA + c] = v.x;
    As[(q * 4 + 1) * ASA + c] = v.y;
    As[(q * 4 + 2) * ASA + c] = v.z;
    As[(q * 4 + 3) * ASA + c] = v.w;
  }
  __syncthreads();
  // ---- per-pixel inv norm (8 threads per pixel) ----
  {
    int pp = tid >> 3, part = tid & 7;
    float s = 0.f;
    #pragma unroll
    for (int c = 0; c < 16; c++) { float v = As[pp * ASA + part + c * 8]; s += v * v; }
    s += __shfl_down_sync(0xffffffffu, s, 4);
    s += __shfl_down_sync(0xffffffffu, s, 2);
    s += __shfl_down_sync(0xffffffffu, s, 1);
    if (part == 0) inv_s[pp] = 1.0f / fmaxf(sqrtf(s), 1e-12f);
  }
  __syncthreads();
  if (tid < 64) g_inv[(size_t)n * Pp + p0 + tid] = inv_s[tid];
  // ---- scale + tf32 convert in place (pixel-major mapping) ----
  {
    int pp = tid >> 3, part = tid & 7;
    float iv = inv_s[pp];
    #pragma unroll
    for (int i = 0; i < 16; i++) {
      int c = part * 16 + i;
      As[pp * ASA + c] = f2tf(As[pp * ASA + c] * iv);
    }
  }
  __syncthreads();

  // ---- GEMM: 4 k-chunks of 32 ----
  float acc[2][8][4];
  #pragma unroll
  for (int mf = 0; mf < 2; mf++)
    #pragma unroll
    for (int nf = 0; nf < 8; nf++)
      #pragma unroll
      for (int q = 0; q < 4; q++) acc[mf][nf][q] = 0.f;

  #pragma unroll 1
  for (int kc = 0; kc < 128; kc += 32) {
    // B: 512 j x 32 k (8 float4 per thread)
    #pragma unroll
    for (int i = 0; i < 8; i++) {
      int idx = i * 512 + tid;
      int j = idx >> 3, q = idx & 7;
      float4 v = *(const float4*)(g_wall + (size_t)j * 128 + kc + q * 4);
      float* d = Bs + j * 36 + q * 4;
      d[0] = f2tf(v.x); d[1] = f2tf(v.y); d[2] = f2tf(v.z); d[3] = f2tf(v.w);
    }
    __syncthreads();
    #pragma unroll
    for (int ks = 0; ks < 4; ks++) {
      int kb = kc + ks * 8;
      uint32_t a[2][4];
      #pragma unroll
      for (int mf = 0; mf < 2; mf++) {
        const float* ap = As + (mh + mf * 16 + gr) * ASA + kb + gc;
        a[mf][0] = __float_as_uint(ap[0]);
        a[mf][1] = __float_as_uint(ap[8 * ASA]);
        a[mf][2] = __float_as_uint(ap[4]);
        a[mf][3] = __float_as_uint(ap[8 * ASA + 4]);
      }
      #pragma unroll
      for (int nf = 0; nf < 8; nf++) {
        const float* bp = Bs + (jb + nf * 8 + gr) * 36 + (ks * 8) + gc;
        uint32_t b0 = __float_as_uint(bp[0]);
        uint32_t b1 = __float_as_uint(bp[4]);
        #pragma unroll
        for (int mf = 0; mf < 2; mf++)
          MMA_TF32(acc[mf][nf], a[mf][0], a[mf][1], a[mf][2], a[mf][3], b0, b1);
      }
    }
    __syncthreads();
  }

  // ---- stage scores into Ssc[64][513] (aliases As/Bs) ----
  #pragma unroll
  for (int mf = 0; mf < 2; mf++)
    #pragma unroll
    for (int nf = 0; nf < 8; nf++) {
      int r0 = mh + mf * 16 + gr;
      int cb = jb + nf * 8 + 2 * gc;
      Ssc[r0 * SST + cb]           = acc[mf][nf][0];
      Ssc[r0 * SST + cb + 1]       = acc[mf][nf][1];
      Ssc[(r0 + 8) * SST + cb]     = acc[mf][nf][2];
      Ssc[(r0 + 8) * SST + cb + 1] = acc[mf][nf][3];
    }
  // ---- per-pixel window masks (while staging completes) ----
  if (tid < 64) {
    int p = p0 + tid;
    int h = p / Ww, ww = p % Ww;
    msk[tid][0] = (h < 32) ? 1.f : 0.f;
    msk[tid][1] = (h >= 16) ? 1.f : 0.f;
    msk[tid][2] = (ww < 32) ? 1.f : 0.f;
    msk[tid][3] = (ww >= 16) ? 1.f : 0.f;
    msk[tid][4] = (h < 19) ? 1.f : 0.f;
    msk[tid][5] = (h >= 9 && h < 29) ? 1.f : 0.f;
    msk[tid][6] = (h >= 19 && h < 39) ? 1.f : 0.f;
    msk[tid][7] = (h >= 29) ? 1.f : 0.f;
    msk[tid][8] = (ww < 19) ? 1.f : 0.f;
    msk[tid][9] = (ww >= 9 && ww < 29) ? 1.f : 0.f;
    msk[tid][10] = (ww >= 19 && ww < 39) ? 1.f : 0.f;
    msk[tid][11] = (ww >= 29) ? 1.f : 0.f;
  }
  __syncthreads();

  // ---- per-pixel epilogue: warp w owns pixels w*4 .. w*4+3 ----
  #pragma unroll
  for (int i = 0; i < 4; i++) {
    int pp = w * 4 + i;
    float* row = Ssc + pp * SST;
    float s1 = row[lane], s2 = row[lane + 32];
    float mx = fmaxf(s1, s2);
    #pragma unroll
    for (int o = 16; o; o >>= 1) mx = fmaxf(mx, __shfl_xor_sync(0xffffffffu, mx, o));
    float e1 = __expf(s1 - mx), e2 = __expf(s2 - mx);
    float z = e1 + e2;
    #pragma unroll
    for (int o = 16; o; o >>= 1) z += __shfl_xor_sync(0xffffffffu, z, o);
    float a1 = e1 / z, a2 = e2 / z;

    #pragma unroll
    for (int half = 0; half < 2; half++) {
      int k = lane + half * 32;
      float s = half ? s2 : s1;
      float h0 = row[64 + k * 4 + 0], h1 = row[64 + k * 4 + 1];
      float h2 = row[64 + k * 4 + 2], h3 = row[64 + k * 4 + 3];
      float mxs = fmaxf(fmaxf(fmaxf(h0, h1), fmaxf(h2, h3)), s);
      float es = __expf(s - mxs);
      float d = es + __expf(h0 - mxs) + __expf(h1 - mxs) + __expf(h2 - mxs) + __expf(h3 - mxs);
      float av = (half ? a2 : a1) * (es / d);
      row[k] = av;                      // overwrite score with final a
    }
  }
  __syncthreads();

  // ---- coalesced g_a stores: 64 k x 64 p ----
  #pragma unroll
  for (int i = 0; i < 8; i++) {
    int idx = i * 512 + tid;
    int k = idx >> 6, pp = idx & 63;
    g_a[((size_t)n * Kk + k) * Pp + p0 + pp] = Ssc[pp * SST + k];
  }

  // ---- region-sum partials -> atomicAdd g_sal ----
  // thread t < 384: jj = t>>1 (0..191), pixel half = t&1
  if (tid < 384) {
    int jj = tid >> 1, half = tid & 1;
    int lev = jj >> 6, k = jj & 63;
    int pbeg = half * 32, pend = pbeg + 32;
    float* base = g_sal + ((size_t)n * Kk + k) * Rr;
    if (lev == 0) {
      float s = 0.f;
      for (int pp = pbeg; pp < pend; pp++)
        s += fmaxf(Ssc[pp * SST + 320 + jj], 0.f);
      atomicAdd(base + 0, s);
    } else if (lev == 1) {
      float a4[4] = {};
      for (int pp = pbeg; pp < pend; pp++) {
        float v = fmaxf(Ssc[pp * SST + 320 + jj], 0.f);
        float t0 = v * msk[pp][0], t1 = v * msk[pp][1];
        float w0 = msk[pp][2], w1 = msk[pp][3];
        a4[0] += t0 * w0; a4[1] += t0 * w1;
        a4[2] += t1 * w0; a4[3] += t1 * w1;
      }
      #pragma unroll
      for (int r = 0; r < 4; r++) atomicAdd(base + 1 + r, a4[r]);
    } else {
      float a16[16] = {};
      for (int pp = pbeg; pp < pend; pp++) {
        float v = fmaxf(Ssc[pp * SST + 320 + jj], 0.f);
        float t0 = v * msk[pp][4], t1 = v * msk[pp][5];
        float t2 = v * msk[pp][6], t3 = v * msk[pp][7];
        float w0 = msk[pp][8], w1 = msk[pp][9], w2 = msk[pp][10], w3 = msk[pp][11];
        a16[0]  += t0 * w0; a16[1]  += t0 * w1; a16[2]  += t0 * w2; a16[3]  += t0 * w3;
        a16[4]  += t1 * w0; a16[5]  += t1 * w1; a16[6]  += t1 * w2; a16[7]  += t1 * w3;
        a16[8]  += t2 * w0; a16[9]  += t2 * w1; a16[10] += t2 * w2; a16[11] += t2 * w3;
        a16[12] += t3 * w0; a16[13] += t3 * w1; a16[14] += t3 * w2; a16[15] += t3 * w3;
      }
      #pragma unroll
      for (int r = 0; r < 16; r++) atomicAdd(base + 5 + r, a16[r]);
    }
  }
}

// ---------------- K7: vlad via tf32 mma.sync (split-B) + awsum --------------
#define VSAL_OFF 0
#define VA_OFF   (64 * 22)                 // 1408
#define VBH_OFF  (VA_OFF + 64 * 36)        // 3712
#define VBL_OFF  (VBH_OFF + 128 * 36)      // 8320
#define SMEM_V   ((VBL_OFF + 128 * 36) * 4)  // 51712 B

__global__ void __launch_bounds__(256) k_vlad(const float* __restrict__ x) {
  extern __shared__ float sm[];
  float* salsh = sm + VSAL_OFF;          // [64][22]
  float* As    = sm + VA_OFF;            // [64][36]  aw tf32
  float* Bh    = sm + VBH_OFF;           // [128][36] xn hi tf32
  float* Bl    = sm + VBL_OFF;           // [128][36] xn lo tf32
  __shared__ unsigned char msh[8][32];
  __shared__ float iv[32];

  int tid = threadIdx.x, lane = tid & 31, w = tid >> 5;
  int gr = lane >> 2, gc = lane & 3;
  int n = blockIdx.y, chk = blockIdx.x;
  int p0base = chk * (Pp / NCH);

  for (int i = tid; i < 64 * 21; i += 256)
    salsh[(i / 21) * 22 + (i % 21)] = g_sal[(size_t)n * Kk * Rr + i];

  float acc[8][4];
  #pragma unroll
  for (int nf = 0; nf < 8; nf++)
    #pragma unroll
    for (int q = 0; q < 4; q++) acc[nf][q] = 0.f;
  float regsum[8] = {};

  #pragma unroll 1
  for (int t = 0; t < 6; t++) {
    int p0 = p0base + t * 32;
    __syncthreads();                      // prior mma reads done
    if (tid < 32) {
      int p = p0 + tid;
      iv[tid] = g_inv[(size_t)n * Pp + p];
      int h = p / Ww, wq = p % Ww;
      int a, b;
      memb1(h, a, b);  msh[0][tid] = a; msh[1][tid] = b;
      memb1(wq, a, b); msh[2][tid] = a; msh[3][tid] = b;
      memb2(h, a, b);  msh[4][tid] = a; msh[5][tid] = b;
      memb2(wq, a, b); msh[6][tid] = a; msh[7][tid] = b;
    }
    __syncthreads();
    // B tiles: [c][pp] from raw x (channel-major, p-contiguous => coalesced)
    #pragma unroll
    for (int i = 0; i < 4; i++) {
      int idx = i * 256 + tid;
      int c = idx >> 3, q = idx & 7;
      float4 v = *(const float4*)(x + ((size_t)n * Cc + c) * Pp + p0 + q * 4);
      float x0 = v.x * iv[q * 4 + 0], x1 = v.y * iv[q * 4 + 1];
      float x2 = v.z * iv[q * 4 + 2], x3 = v.w * iv[q * 4 + 3];
      float h0 = f2tf(x0), h1 = f2tf(x1), h2 = f2tf(x2), h3 = f2tf(x3);
      *(float4*)(Bh + c * 36 + q * 4) = make_float4(h0, h1, h2, h3);
      *(float4*)(Bl + c * 36 + q * 4) =
          make_float4(f2tf(x0 - h0), f2tf(x1 - h1), f2tf(x2 - h2), f2tf(x3 - h3));
    }
    // aw tile: k = i*8 + w, pp = lane
    #pragma unroll
    for (int i = 0; i < 8; i++) {
      int k = i * 8 + w;
      float av = g_a[((size_t)n * Kk + k) * Pp + p0 + lane];
      const float* sk = salsh + k * 22;
      float wsum = sk[0];
      int r1l = msh[0][lane], r1h = msh[1][lane], c1l = msh[2][lane], c1h = msh[3][lane];
      int r2l = msh[4][lane], r2h = msh[5][lane], c2l = msh[6][lane], c2h = msh[7][lane];
      for (int ii = r1l; ii <= r1h; ii++)
        for (int jj = c1l; jj <= c1h; jj++) wsum += sk[1 + 2 * ii + jj];
      for (int ii = r2l; ii <= r2h; ii++)
        for (int jj = c2l; jj <= c2h; jj++) wsum += sk[5 + 4 * ii + jj];
      float aw = f2tf(av * wsum);          // tf32 value used in BOTH mma and awsum
      As[k * 36 + lane] = aw;
      regsum[i] += aw;
    }
    __syncthreads();
    // mma: warp w -> m-frag (w>>1) [16 k], c-half (w&1) [64 c]
    #pragma unroll
    for (int ks = 0; ks < 4; ks++) {
      int kb = ks * 8;
      const float* ap = As + ((w >> 1) * 16 + gr) * 36 + kb + gc;
      uint32_t a0 = __float_as_uint(ap[0]);
      uint32_t a1 = __float_as_uint(ap[8 * 36]);
      uint32_t a2 = __float_as_uint(ap[4]);
      uint32_t a3 = __float_as_uint(ap[8 * 36 + 4]);
      #pragma unroll
      for (int nf = 0; nf < 8; nf++) {
        int crow = (w & 1) * 64 + nf * 8 + gr;
        const float* bph = Bh + crow * 36 + kb + gc;
        const float* bpl = Bl + crow * 36 + kb + gc;
        MMA_TF32(acc[nf], a0, a1, a2, a3,
                 __float_as_uint(bph[0]), __float_as_uint(bph[4]));
        MMA_TF32(acc[nf], a0, a1, a2, a3,
                 __float_as_uint(bpl[0]), __float_as_uint(bpl[4]));
      }
    }
  }

  // ---- store partials ----
  float* outp = g_part + ((size_t)n * NCH + chk) * Kk * Cc;
  #pragma unroll
  for (int nf = 0; nf < 8; nf++) {
    int r = (w >> 1) * 16 + gr;
    int col = (w & 1) * 64 + nf * 8 + 2 * gc;
    outp[r * 128 + col]           = acc[nf][0];
    outp[r * 128 + col + 1]       = acc[nf][1];
    outp[(r + 8) * 128 + col]     = acc[nf][2];
    outp[(r + 8) * 128 + col + 1] = acc[nf][3];
  }
  // ---- awsum: lanes of warp w share k = i*8 + w ----
  #pragma unroll
  for (int i = 0; i < 8; i++) {
    float s = regsum[i];
    #pragma unroll
    for (int o = 16; o; o >>= 1) s += __shfl_xor_sync(0xffffffffu, s, o);
    if (lane == 0) atomicAdd(&g_awsum[n * Kk + i * 8 + w], s);
  }
}

// ---------------- K8: reduce partials, subtract centroid, intra-norm ---------
__global__ void k_fin1(const float* __restrict__ centroids,
                       const float* __restrict__ cw, float* __restrict__ out) {
  int k = blockIdx.x, n = blockIdx.y, c = threadIdx.x;   // 128 threads
  float s = 0.f;
  #pragma unroll
  for (int ch = 0; ch < NCH; ch++)
    s += g_part[(((size_t)n * NCH + ch) * Kk + k) * Cc + c];
  float v = s - centroids[k * 128 + c] * g_awsum[n * Kk + k];
  __shared__ float red[128];
  __shared__ float invs;
  red[c] = v * v; __syncthreads();
  for (int off = 64; off; off >>= 1) {
    if (c < off) red[c] += red[c + off];
    __syncthreads();
  }
  if (c == 0) invs = 1.0f / fmaxf(sqrtf(red[0]), 1e-12f);
  __syncthreads();
  float val = v * invs * cw[k];
  out[(size_t)n * (Kk * Cc) + k * 128 + c] = val;
  red[c] = val * val; __syncthreads();
  for (int off = 64; off; off >>= 1) {
    if (c < off) red[c] += red[c + off];
    __syncthreads();
  }
  if (c == 0) atomicAdd(&g_nrm[n], red[0]);
}

// ---------------- K9: global normalization ----------------------------------
__global__ void k_fin2(float* __restrict__ out) {
  int n = blockIdx.y;
  int i = blockIdx.x * 256 + threadIdx.x;
  float inv = 1.0f / fmaxf(sqrtf(g_nrm[n]), 1e-12f);
  out[(size_t)n * (Kk * Cc) + i] *= inv;
}

// ---------------- launcher ---------------------------------------------------
extern "C" void kernel_launch(void* const* d_in, const int* in_sizes, int n_in,
                              void* d_out, int out_size) {
  const float* x         = (const float*)d_in[0];  // [N,C,H,W]
  const float* centroids = (const float*)d_in[1];  // [K,C]
  const float* conv_w    = (const float*)d_in[2];  // [K,C]
  const float* shadow_w  = (const float*)d_in[3];  // [K*S,C]
  const float* app_w     = (const float*)d_in[4];  // [L,K,C]
  const float* clw       = (const float*)d_in[5];  // [K]
  float* out = (float*)d_out;

  cudaFuncSetAttribute(k_gemm_epi, cudaFuncAttributeMaxDynamicSharedMemorySize, SMEM_K3);
  cudaFuncSetAttribute(k_vlad, cudaFuncAttributeMaxDynamicSharedMemorySize, SMEM_V);

  k_wall<<<dim3((Jj * Cc + 255) / 256), 256>>>(conv_w, shadow_w, app_w);
  k_gemm_epi<<<MTOT / 64, 512, SMEM_K3>>>(x);
  k_vlad<<<dim3(NCH, Nn), 256, SMEM_V>>>(x);
  k_fin1<<<dim3(Kk, Nn), 128>>>(centroids, clw, out);
  k_fin2<<<dim3(Kk * Cc / 256, Nn), 256>>>(out);
}